// round 12
// baseline (speedup 1.0000x reference)
#include <cuda_runtime.h>
#include <cuda_fp16.h>
#include <cstdint>

// ---------------- problem constants (fixed by setup_inputs) ----------------
#define B_SZ   2
#define N_TOK  32768
#define DIM    512
#define HEADS  8
#define DH     64
#define NGRAPH 32
#define QKV3   1536
#define M_ROWS (B_SZ * N_TOK)          // 65536
#define KDIM   512
#define TILEMAX 288                    // max token-tiles per batch

// ---------------- device scratch (static; no allocations allowed) ----------
__device__ __half g_a_hi[(size_t)M_ROWS * KDIM];
__device__ __half g_b1_hi[QKV3 * KDIM];
__device__ __half g_b2_hi[DIM * KDIM];
__device__ __half g_q_hi[((size_t)M_ROWS + 128) * DIM];   // +128 slack rows
__device__ __half g_q_lo[((size_t)M_ROWS + 128) * DIM];
__device__ __half g_k_hi[(size_t)M_ROWS * DIM];
__device__ __half g_k_lo[(size_t)M_ROWS * DIM];
__device__ __half g_v_hi[(size_t)M_ROWS * DIM];
__device__ __half g_v_lo[(size_t)M_ROWS * DIM];
__device__ __half g_attn_hi[(size_t)M_ROWS * DIM];
__device__ __half g_ktvT_hi[B_SZ * HEADS * NGRAPH * DH * DH];
__device__ __half g_ktvT_lo[B_SZ * HEADS * NGRAPH * DH * DH];
__device__ int    g_sizes[NGRAPH];
__device__ int    g_off [NGRAPH + 1];
__device__ int    g_tile_g[TILEMAX];
__device__ int    g_tile_tok0[TILEMAX];
__device__ int    g_tile_nval[TILEMAX];

// ---------------- helpers ---------------------------------------------------
__device__ __forceinline__ uint32_t smem_u32(const void* p) {
    uint32_t a;
    asm("{ .reg .u64 t; cvta.to.shared.u64 t, %1; cvt.u32.u64 %0, t; }"
        : "=r"(a) : "l"(p));
    return a;
}
__device__ __forceinline__ void mma16816(float* d, const uint32_t* a, const uint32_t* b) {
    asm volatile(
        "mma.sync.aligned.m16n8k16.row.col.f32.f16.f16.f32 "
        "{%0,%1,%2,%3}, {%4,%5,%6,%7}, {%8,%9}, {%0,%1,%2,%3};"
        : "+f"(d[0]), "+f"(d[1]), "+f"(d[2]), "+f"(d[3])
        : "r"(a[0]), "r"(a[1]), "r"(a[2]), "r"(a[3]), "r"(b[0]), "r"(b[1]));
}
#define LDMX4(r, addr) \
    asm volatile("ldmatrix.sync.aligned.m8n8.x4.shared.b16 {%0,%1,%2,%3}, [%4];" \
                 : "=r"((r)[0]), "=r"((r)[1]), "=r"((r)[2]), "=r"((r)[3]) : "r"(addr))
#define LDMX4T(r, addr) \
    asm volatile("ldmatrix.sync.aligned.m8n8.x4.trans.shared.b16 {%0,%1,%2,%3}, [%4];" \
                 : "=r"((r)[0]), "=r"((r)[1]), "=r"((r)[2]), "=r"((r)[3]) : "r"(addr))
#define CPA16(s, gp) \
    asm volatile("cp.async.cg.shared.global [%0], [%1], 16;" :: "r"(s), "l"(gp))

// ---------------- hist + tile tables ----------------------------------------
__global__ void hist_kernel(const int* __restrict__ batch) {
    __shared__ int cnt[NGRAPH];
    int tid = threadIdx.x;
    if (tid < NGRAPH) cnt[tid] = 0;
    __syncthreads();
    for (int i = tid; i < N_TOK; i += 256) atomicAdd(&cnt[batch[i]], 1);
    __syncthreads();
    if (tid == 0) {
        int off = 0;
        for (int g = 0; g < NGRAPH; g++) {
            g_off[g] = off; g_sizes[g] = cnt[g]; off += cnt[g];
        }
        g_off[NGRAPH] = off;
        int t = 0;
        for (int g = 0; g < NGRAPH; g++) {
            int S = g_sizes[g];
            for (int i = 0; i < S; i += 128) {
                g_tile_g[t] = g;
                g_tile_tok0[t] = g_off[g] + i;
                g_tile_nval[t] = (S - i < 128) ? (S - i) : 128;
                t++;
            }
        }
        for (; t < TILEMAX; t++) g_tile_nval[t] = 0;
    }
}

__device__ __forceinline__ void split2(float f0, float f1, ushort2& uh, ushort2& ul) {
    __half h0 = __float2half_rn(f0), h1 = __float2half_rn(f1);
    __half l0 = __float2half_rn(f0 - __half2float(h0));
    __half l1 = __float2half_rn(f1 - __half2float(h1));
    uh = make_ushort2(__half_as_ushort(h0), __half_as_ushort(h1));
    ul = make_ushort2(__half_as_ushort(l0), __half_as_ushort(l1));
}
__device__ __forceinline__ ushort4 round4(float4 v) {
    ushort4 r;
    r.x = __half_as_ushort(__float2half_rn(v.x));
    r.y = __half_as_ushort(__float2half_rn(v.y));
    r.z = __half_as_ushort(__float2half_rn(v.z));
    r.w = __half_as_ushort(__float2half_rn(v.w));
    return r;
}

// fp32 -> fp16 round, x4
__global__ void conv_round_kernel(const float* __restrict__ src,
                                  __half* __restrict__ dst, long n4) {
    long i = (long)blockIdx.x * blockDim.x + threadIdx.x;
    long stride = (long)gridDim.x * blockDim.x;
    for (; i < n4; i += stride)
        ((ushort4*)dst)[i] = round4(((const float4*)src)[i]);
}

// weights: fp16 rounding, one launch
__global__ void conv_w_kernel(const float* __restrict__ w1,
                              const float* __restrict__ w2) {
    const long n1 = (long)QKV3 * KDIM / 4;
    const long n2 = (long)DIM * KDIM / 4;
    long i = (long)blockIdx.x * blockDim.x + threadIdx.x;
    long stride = (long)gridDim.x * blockDim.x;
    for (; i < n1 + n2; i += stride) {
        if (i < n1) ((ushort4*)g_b1_hi)[i]      = round4(((const float4*)w1)[i]);
        else        ((ushort4*)g_b2_hi)[i - n1] = round4(((const float4*)w2)[i - n1]);
    }
}

#define TEN_BYTES (128 * 144)

__device__ __forceinline__ void issue_slab(uint32_t sdst, const __half* g,
                                           int k0, int tid) {
#pragma unroll
    for (int t = 0; t < 4; t++) {
        int id  = tid + t * 256;
        int row = id >> 3, col = id & 7;
        CPA16(sdst + row * 144 + col * 16, g + (size_t)row * KDIM + k0 + col * 8);
    }
}
// 256-row slab (for GEMM1 B tile)
__device__ __forceinline__ void issue_slab256(uint32_t sdst, const __half* g,
                                              int k0, int tid) {
#pragma unroll
    for (int t = 0; t < 8; t++) {
        int id  = tid + t * 256;
        int row = id >> 3, col = id & 7;
        CPA16(sdst + row * 144 + col * 16, g + (size_t)row * KDIM + k0 + col * 8);
    }
}

// ---------------- GEMM1: qkv = x16 @ w16^T (1-term, warp tile 64x64) --------
// CTA tile 128x256, 8 warps (2M x 4N), 3-stage ring, 1 CTA/SM.
// epilogue: q scale->split, k LN(ln1)->split, v LN(ln2)->split
#define QA_BYTES (128 * 144)              // 18432
#define QB_BYTES (256 * 144)              // 36864
#define QSTG     (QA_BYTES + QB_BYTES)    // 55296
#define QK_SMEM  (3 * QSTG)               // 165888

__global__ __launch_bounds__(256, 1)
void qkv_gemm_kernel(const __half* __restrict__ Ah, const __half* __restrict__ Bh,
                     const int* __restrict__ batch,
                     const float* __restrict__ ln1w, const float* __restrict__ ln1b,
                     const float* __restrict__ ln2w, const float* __restrict__ ln2b) {
    extern __shared__ __align__(16) char smem[];
    uint32_t sb = smem_u32(smem);
    int tid = threadIdx.x, wid = tid >> 5, lane = tid & 31;
    int warpM = (wid & 1) * 64;       // 2 warps along M
    int warpN = (wid >> 1) * 64;      // 4 warps along N (one head each)
    int g = lane >> 2, c2 = lane & 3;

    uint32_t aoff = (lane & 15) * 144 + (lane >> 4) * 16;
    uint32_t boff = ((lane & 7) + ((lane >> 4) << 3)) * 144 + ((lane >> 3) & 1) * 16;

    const __half* pAh = Ah + (size_t)blockIdx.y * 128 * KDIM;
    const __half* pBh = Bh + (size_t)blockIdx.x * 256 * KDIM;

#define QST_A(s) (sb + (s) * QSTG)
#define QST_B(s) (sb + (s) * QSTG + QA_BYTES)
#define Q_ISSUE(s, k0)                               \
    do {                                             \
        issue_slab(QST_A(s), pAh, (k0), tid);        \
        issue_slab256(QST_B(s), pBh, (k0), tid);     \
        asm volatile("cp.async.commit_group;");      \
    } while (0)

    Q_ISSUE(0, 0);
    Q_ISSUE(1, 64);

    float acc[4][8][4];
#pragma unroll
    for (int i = 0; i < 4; i++)
#pragma unroll
        for (int j = 0; j < 8; j++)
#pragma unroll
            for (int k = 0; k < 4; k++) acc[i][j][k] = 0.0f;

    for (int it = 0; it < 8; it++) {
        int s = it % 3;
        if (it < 7) asm volatile("cp.async.wait_group 1;");
        else        asm volatile("cp.async.wait_group 0;");
        __syncthreads();   // single barrier (3-stage ring, proven pattern)
        uint32_t aA0 = QST_A(s) + warpM * 144 + aoff;
        uint32_t aB0 = QST_B(s) + warpN * 144 + boff;
#pragma unroll
        for (int kk = 0; kk < 4; kk++) {
            int ko = kk * 32;
            uint32_t ah[4][4], bf[4][4];
#pragma unroll
            for (int p = 0; p < 4; p++) LDMX4(ah[p], aA0 + p * 16 * 144 + ko);
#pragma unroll
            for (int p = 0; p < 4; p++) LDMX4(bf[p], aB0 + p * 16 * 144 + ko);
#pragma unroll
            for (int mt = 0; mt < 4; mt++)
#pragma unroll
                for (int nt = 0; nt < 8; nt++)
                    mma16816(acc[mt][nt], ah[mt], &bf[nt >> 1][(nt & 1) * 2]);
        }
        if (it + 2 < 8) Q_ISSUE((it + 2) % 3, (it + 2) * 64);
    }

    // epilogue: q scale+split / k,v LN+split (each warp = one 64-col head)
    int mode = blockIdx.x >> 1;          // 0 q, 1 k, 2 v
    const float* lw = (mode == 1) ? ln1w : ln2w;
    const float* lb = (mode == 1) ? ln1b : ln2b;
    __half* dh = (mode == 0) ? g_q_hi : (mode == 1) ? g_k_hi : g_v_hi;
    __half* dl = (mode == 0) ? g_q_lo : (mode == 1) ? g_k_lo : g_v_lo;
    int colbase = (blockIdx.x & 1) * 256 + warpN;   // 0..448, buffer-local
#pragma unroll
    for (int mt = 0; mt < 4; mt++) {
#pragma unroll
        for (int hf = 0; hf < 2; hf++) {
            size_t m = (size_t)blockIdx.y * 128 + warpM + mt * 16 + g + hf * 8;
            float v[16];
#pragma unroll
            for (int nt = 0; nt < 8; nt++) {
                v[nt * 2]     = acc[mt][nt][hf * 2];
                v[nt * 2 + 1] = acc[mt][nt][hf * 2 + 1];
            }
            if (mode == 0) {
                int n = (int)(m & (N_TOK - 1));
                float sc = 1.0f / (float)g_sizes[batch[n]];
#pragma unroll
                for (int k = 0; k < 16; k++) v[k] *= sc;
            } else {
                float s = 0.f, s2 = 0.f;
#pragma unroll
                for (int k = 0; k < 16; k++) { s += v[k]; s2 += v[k] * v[k]; }
                s  += __shfl_xor_sync(0xffffffffu, s, 1);
                s  += __shfl_xor_sync(0xffffffffu, s, 2);
                s2 += __shfl_xor_sync(0xffffffffu, s2, 1);
                s2 += __shfl_xor_sync(0xffffffffu, s2, 2);
                float mu = s * (1.0f / 64.0f);
                float var = s2 * (1.0f / 64.0f) - mu * mu;
                float rs = rsqrtf(var + 1e-6f);
#pragma unroll
                for (int nt = 0; nt < 8; nt++) {
                    int cl = nt * 8 + c2 * 2;   // head-local col (warp = 1 head)
                    v[nt * 2]     = (v[nt * 2]     - mu) * rs * lw[cl]     + lb[cl];
                    v[nt * 2 + 1] = (v[nt * 2 + 1] - mu) * rs * lw[cl + 1] + lb[cl + 1];
                }
            }
            size_t base = m * DIM + colbase + c2 * 2;
#pragma unroll
            for (int nt = 0; nt < 8; nt++) {
                ushort2 uh, ul;
                split2(v[nt * 2], v[nt * 2 + 1], uh, ul);
                *(ushort2*)((unsigned short*)dh + base + nt * 8) = uh;
                *(ushort2*)((unsigned short*)dl + base + nt * 8) = ul;
            }
        }
    }
#undef QST_A
#undef QST_B
#undef Q_ISSUE
}

// ---------------- GEMM2: out = attn_hi @ w_out^T + bias (1-term) ------------
#define OG_SMEM (2 * 2 * TEN_BYTES)   // 73728

__global__ __launch_bounds__(256, 2)
void out_gemm_kernel(const __half* __restrict__ Ah, const __half* __restrict__ Bh,
                     float* __restrict__ C, const float* __restrict__ bias) {
    extern __shared__ __align__(16) char smem[];
    uint32_t sb = smem_u32(smem);
    int tid = threadIdx.x, wid = tid >> 5, lane = tid & 31;
    int warpM = (wid & 3) * 32;
    int warpN = (wid >> 2) * 64;
    int g = lane >> 2, c2 = lane & 3;

    uint32_t aoff = (lane & 15) * 144 + (lane >> 4) * 16;
    uint32_t boff = ((lane & 7) + ((lane >> 4) << 3)) * 144 + ((lane >> 3) & 1) * 16;

    const __half* pAh = Ah + (size_t)blockIdx.y * 128 * KDIM;
    const __half* pBh = Bh + (size_t)blockIdx.x * 128 * KDIM;

#define OST(s, t) (sb + ((s) * 2 + (t)) * TEN_BYTES)
#define O_ISSUE(s, k0)                            \
    do {                                          \
        issue_slab(OST(s, 0), pAh, (k0), tid);    \
        issue_slab(OST(s, 1), pBh, (k0), tid);    \
        asm volatile("cp.async.commit_group;");   \
    } while (0)

    O_ISSUE(0, 0);
    O_ISSUE(1, 64);

    float acc[2][8][4];
#pragma unroll
    for (int i = 0; i < 2; i++)
#pragma unroll
        for (int j = 0; j < 8; j++)
#pragma unroll
            for (int k = 0; k < 4; k++) acc[i][j][k] = 0.0f;

    for (int it = 0; it < 8; it++) {
        int s = it & 1;
        if (it < 7) asm volatile("cp.async.wait_group 1;");
        else        asm volatile("cp.async.wait_group 0;");
        __syncthreads();
        uint32_t aA0 = OST(s, 0) + warpM * 144 + aoff;
        uint32_t aB0 = OST(s, 1) + warpN * 144 + boff;
#pragma unroll
        for (int kk = 0; kk < 4; kk++) {
            int ko = kk * 32;
            uint32_t ah[2][4], bf[4][4];
            LDMX4(ah[0], aA0 + ko); LDMX4(ah[1], aA0 + 16 * 144 + ko);
#pragma unroll
            for (int p = 0; p < 4; p++) LDMX4(bf[p], aB0 + p * 16 * 144 + ko);
#pragma unroll
            for (int mt = 0; mt < 2; mt++)
#pragma unroll
                for (int nt = 0; nt < 8; nt++)
                    mma16816(acc[mt][nt], ah[mt], &bf[nt >> 1][(nt & 1) * 2]);
        }
        __syncthreads();
        if (it + 2 < 8) O_ISSUE(s, (it + 2) * 64);
    }

#pragma unroll
    for (int mt = 0; mt < 2; mt++) {
        size_t m0 = (size_t)blockIdx.y * 128 + warpM + mt * 16 + g;
#pragma unroll
        for (int nt = 0; nt < 8; nt++) {
            int nc = blockIdx.x * 128 + warpN + nt * 8 + c2 * 2;
            float b0 = bias[nc], b1 = bias[nc + 1];
            *(float2*)(C + m0 * DIM + nc) =
                make_float2(acc[mt][nt][0] + b0, acc[mt][nt][1] + b1);
            *(float2*)(C + (m0 + 8) * DIM + nc) =
                make_float2(acc[mt][nt][2] + b0, acc[mt][nt][3] + b1);
        }
    }
#undef OST
#undef O_ISSUE
}

// ---------------- ktvT[b,h,g] (tensor, 3-term, ldmatrix.trans) --------------
#define KT_SLAB  (64 * 144)
#define KT_STAGE (4 * KT_SLAB)
#define KT_SMEM  (2 * KT_STAGE)      // 73728

__global__ __launch_bounds__(128, 2)
void ktvmma_kernel() {
    int gseg = blockIdx.x & 31;
    int h = (blockIdx.x >> 5) & 7;
    int b = blockIdx.x >> 8;
    int s0 = g_off[gseg], s1 = g_off[gseg + 1];
    int NCH = (s1 - s0 + 63) >> 6;
    if (NCH <= 0) NCH = 1;

    extern __shared__ __align__(16) char smem[];
    uint32_t sb = smem_u32(smem);
    int tid = threadIdx.x, wid = tid >> 5, lane = tid & 31;
    int lg = lane >> 2, c2 = lane & 3;

#define KT_ISSUE(st, c)                                                        \
    do {                                                                       \
        int t0 = s0 + (c) * 64;                                                \
        uint32_t base = sb + (st) * KT_STAGE;                                  \
        char* cbase = smem + (st) * KT_STAGE;                                  \
        _Pragma("unroll")                                                      \
        for (int i = 0; i < 4; i++) {                                          \
            int id = tid + i * 128;                                            \
            int row = id >> 3, ch = id & 7;                                    \
            int tok = t0 + row;                                                \
            uint32_t so = row * 144 + ch * 16;                                 \
            if (tok < s1) {                                                    \
                size_t go = ((size_t)b * N_TOK + tok) * DIM + h * DH + ch * 8; \
                CPA16(base + 0 * KT_SLAB + so, g_k_hi + go);                   \
                CPA16(base + 1 * KT_SLAB + so, g_k_lo + go);                   \
                CPA16(base + 2 * KT_SLAB + so, g_v_hi + go);                   \
                CPA16(base + 3 * KT_SLAB + so, g_v_lo + go);                   \
            } else {                                                           \
                uint4 z = make_uint4(0, 0, 0, 0);                              \
                *(uint4*)(cbase + 0 * KT_SLAB + so) = z;                       \
                *(uint4*)(cbase + 1 * KT_SLAB + so) = z;                       \
                *(uint4*)(cbase + 2 * KT_SLAB + so) = z;                       \
                *(uint4*)(cbase + 3 * KT_SLAB + so) = z;                       \
            }                                                                  \
        }                                                                      \
        asm volatile("cp.async.commit_group;");                                \
    } while (0)

    KT_ISSUE(0, 0);
    if (NCH > 1) KT_ISSUE(1, 1);

    uint32_t aoffT = ((lane & 7) + (lane >> 4) * 8) * 144 + ((lane >> 3) & 1) * 16;
    uint32_t boffT = ((lane & 7) + ((lane >> 3) & 1) * 8) * 144 + (lane >> 4) * 16;

    float acc[8][4];
#pragma unroll
    for (int j = 0; j < 8; j++)
#pragma unroll
        for (int k = 0; k < 4; k++) acc[j][k] = 0.0f;

    for (int c = 0; c < NCH; c++) {
        int st = c & 1;
        if (c + 2 <= NCH) asm volatile("cp.async.wait_group 1;");
        else              asm volatile("cp.async.wait_group 0;");
        __syncthreads();
        uint32_t base = sb + st * KT_STAGE;
        uint32_t aKh = base + 0 * KT_SLAB + boffT;
        uint32_t aKl = base + 1 * KT_SLAB + boffT;
        uint32_t aVh = base + 2 * KT_SLAB + wid * 32 + aoffT;
        uint32_t aVl = base + 3 * KT_SLAB + wid * 32 + aoffT;
#pragma unroll
        for (int kk = 0; kk < 4; kk++) {
            int ko = kk * (16 * 144);
            uint32_t vh[4], vl[4], kh[4][4], kl[4][4];
            LDMX4T(vh, aVh + ko);
            LDMX4T(vl, aVl + ko);
#pragma unroll
            for (int nb = 0; nb < 4; nb++) {
                LDMX4T(kh[nb], aKh + nb * 32 + ko);
                LDMX4T(kl[nb], aKl + nb * 32 + ko);
            }
#pragma unroll
            for (int nt = 0; nt < 8; nt++) {
                mma16816(acc[nt], vh, &kh[nt >> 1][(nt & 1) * 2]);
                mma16816(acc[nt], vl, &kh[nt >> 1][(nt & 1) * 2]);
                mma16816(acc[nt], vh, &kl[nt >> 1][(nt & 1) * 2]);
            }
        }
        __syncthreads();
        if (c + 2 < NCH) KT_ISSUE(st, c + 2);
    }

    size_t kb = (size_t)blockIdx.x * (DH * DH);
    int r0 = wid * 16 + lg;
#pragma unroll
    for (int nt = 0; nt < 8; nt++) {
        int cidx = nt * 8 + c2 * 2;
        ushort2 uh, ul;
        split2(acc[nt][0], acc[nt][1], uh, ul);
        *(ushort2*)((unsigned short*)g_ktvT_hi + kb + (size_t)r0 * DH + cidx) = uh;
        *(ushort2*)((unsigned short*)g_ktvT_lo + kb + (size_t)r0 * DH + cidx) = ul;
        split2(acc[nt][2], acc[nt][3], uh, ul);
        *(ushort2*)((unsigned short*)g_ktvT_hi + kb + (size_t)(r0 + 8) * DH + cidx) = uh;
        *(ushort2*)((unsigned short*)g_ktvT_lo + kb + (size_t)(r0 + 8) * DH + cidx) = ul;
    }
#undef KT_ISSUE
}

// ---------------- attn tile = q_tile @ ktvT (tensor, 3-term, hi-only out) ---
#define AP_QSLAB (128 * 144)
#define AP_TSLAB (64 * 144)
#define AP_SMEM  (2 * AP_QSLAB + 2 * AP_TSLAB)   // 55296

__global__ __launch_bounds__(256, 2)
void applymma_kernel() {
    int h = blockIdx.x, ti = blockIdx.y, b = blockIdx.z;
    int nval = g_tile_nval[ti];
    if (nval == 0) return;
    int gseg = g_tile_g[ti];
    int tok0 = g_tile_tok0[ti];

    extern __shared__ __align__(16) char smem[];
    uint32_t sb = smem_u32(smem);
    uint32_t sQh = sb, sQl = sb + AP_QSLAB;
    uint32_t sTh = sb + 2 * AP_QSLAB, sTl = sTh + AP_TSLAB;

    int tid = threadIdx.x, wid = tid >> 5, lane = tid & 31;
    int warpM = (wid & 3) * 32;
    int warpN = (wid >> 2) * 32;
    int g = lane >> 2, c2 = lane & 3;

    {
        size_t qrow0 = (size_t)b * N_TOK + tok0;
#pragma unroll
        for (int t = 0; t < 4; t++) {
            int id = tid + t * 256;          // 0..1023
            int row = id >> 3, ch = id & 7;
            size_t go = (qrow0 + row) * DIM + h * DH + ch * 8;
            CPA16(sQh + row * 144 + ch * 16, (const __half*)g_q_hi + go);
            CPA16(sQl + row * 144 + ch * 16, (const __half*)g_q_lo + go);
        }
        size_t kbase = ((size_t)((b * HEADS + h) * NGRAPH + gseg)) * DH * DH;
#pragma unroll
        for (int t = 0; t < 2; t++) {
            int id = tid + t * 256;          // 0..511
            int row = id >> 3, ch = id & 7;
            size_t ko = kbase + (size_t)row * DH + ch * 8;
            CPA16(sTh + row * 144 + ch * 16, (const __half*)g_ktvT_hi + ko);
            CPA16(sTl + row * 144 + ch * 16, (const __half*)g_ktvT_lo + ko);
        }
        asm volatile("cp.async.commit_group;");
        asm volatile("cp.async.wait_group 0;");
        __syncthreads();
    }

    uint32_t aoff = (lane & 15) * 144 + (lane >> 4) * 16;
    uint32_t boff = ((lane & 7) + ((lane >> 4) << 3)) * 144 + ((lane >> 3) & 1) * 16;

    float acc[2][4][4];
#pragma unroll
    for (int i = 0; i < 2; i++)
#pragma unroll
        for (int j = 0; j < 4; j++)
#pragma unroll
            for (int k = 0; k < 4; k++) acc[i][j][k] = 0.0f;

    uint32_t aQh = sQh + warpM * 144 + aoff;
    uint32_t aQl = sQl + warpM * 144 + aoff;
    uint32_t aTh = sTh + warpN * 144 + boff;
    uint32_t aTl = sTl + warpN * 144 + boff;

#pragma unroll
    for (int kk = 0; kk < 4; kk++) {
        int ko = kk * 32;
        uint32_t qh[2][4], ql[2][4], bh[2][4], bl[2][4];
        LDMX4(qh[0], aQh + ko); LDMX4(qh[1], aQh + 16 * 144 + ko);
        LDMX4(ql[0], aQl + ko); LDMX4(ql[1], aQl + 16 * 144 + ko);
        LDMX4(bh[0], aTh + ko); LDMX4(bh[1], aTh + 16 * 144 + ko);
        LDMX4(bl[0], aTl + ko); LDMX4(bl[1], aTl + 16 * 144 + ko);
#pragma unroll
        for (int mt = 0; mt < 2; mt++)
#pragma unroll
            for (int nt = 0; nt < 4; nt++) {
                const uint32_t* bph = &bh[nt >> 1][(nt & 1) * 2];
                const uint32_t* bpl = &bl[nt >> 1][(nt & 1) * 2];
                mma16816(acc[mt][nt], qh[mt], bph);
                mma16816(acc[mt][nt], ql[mt], bph);
                mma16816(acc[mt][nt], qh[mt], bpl);
            }
    }

    // masked epilogue -> attn hi only (GEMM2 is 1-term)
#pragma unroll
    for (int mt = 0; mt < 2; mt++) {
#pragma unroll
        for (int hf = 0; hf < 2; hf++) {
            int r = warpM + mt * 16 + g + hf * 8;
            if (r < nval) {
                size_t base = ((size_t)b * N_TOK + tok0 + r) * DIM + h * DH + warpN + c2 * 2;
#pragma unroll
                for (int nt = 0; nt < 4; nt++) {
                    float f0 = acc[mt][nt][hf * 2], f1 = acc[mt][nt][hf * 2 + 1];
                    ushort2 uh = make_ushort2(
                        __half_as_ushort(__float2half_rn(f0)),
                        __half_as_ushort(__float2half_rn(f1)));
                    *(ushort2*)((unsigned short*)g_attn_hi + base + nt * 8) = uh;
                }
            }
        }
    }
}

// ---------------- launch ----------------------------------------------------
extern "C" void kernel_launch(void* const* d_in, const int* in_sizes, int n_in,
                              void* d_out, int out_size) {
    const float* x     = (const float*)d_in[0];
    const float* w_qkv = (const float*)d_in[1];
    const float* ln1w  = (const float*)d_in[2];
    const float* ln1b  = (const float*)d_in[3];
    const float* ln2w  = (const float*)d_in[4];
    const float* ln2b  = (const float*)d_in[5];
    const float* w_out = (const float*)d_in[6];
    const float* b_out = (const float*)d_in[7];
    const int*   batch = (const int*)d_in[8];
    float* out = (float*)d_out;

    __half *ah_p, *b1h_p, *b2h_p, *ath_p;
    cudaGetSymbolAddress((void**)&ah_p,  g_a_hi);
    cudaGetSymbolAddress((void**)&b1h_p, g_b1_hi);
    cudaGetSymbolAddress((void**)&b2h_p, g_b2_hi);
    cudaGetSymbolAddress((void**)&ath_p, g_attn_hi);

    cudaFuncSetAttribute(qkv_gemm_kernel, cudaFuncAttributeMaxDynamicSharedMemorySize, QK_SMEM);
    cudaFuncSetAttribute(out_gemm_kernel, cudaFuncAttributeMaxDynamicSharedMemorySize, OG_SMEM);
    cudaFuncSetAttribute(ktvmma_kernel,   cudaFuncAttributeMaxDynamicSharedMemorySize, KT_SMEM);
    cudaFuncSetAttribute(applymma_kernel, cudaFuncAttributeMaxDynamicSharedMemorySize, AP_SMEM);

    // 0) segment offsets + tile tables
    hist_kernel<<<1, 256>>>(batch);

    // 1) conversions
    conv_round_kernel<<<4096, 256>>>(x, ah_p, (long)M_ROWS * KDIM / 4);
    conv_w_kernel<<<1024, 256>>>(w_qkv, w_out);

    // 2) qkv GEMM (1-term, CTA 128x256, warp 64x64, 3-stage) + fused epilogue
    qkv_gemm_kernel<<<dim3(QKV3 / 256, M_ROWS / 128), 256, QK_SMEM>>>(
        ah_p, b1h_p, batch, ln1w, ln1b, ln2w, ln2b);

    // 3) ktvT per (b,h,g) (tensor, 3-term)
    ktvmma_kernel<<<B_SZ * HEADS * NGRAPH, 128, KT_SMEM>>>();

    // 4) attn = qn @ ktv (tensor, masked ragged tiles) -> attn hi only
    applymma_kernel<<<dim3(HEADS, TILEMAX, B_SZ), 256, AP_SMEM>>>();

    // 5) out = attn_hi @ w_outT + bias (1-term)
    out_gemm_kernel<<<dim3(DIM / 128, M_ROWS / 128), 256, OG_SMEM>>>(
        ath_p, b2h_p, out, b_out);
}

// round 13
// speedup vs baseline: 1.1408x; 1.1408x over previous
#include <cuda_runtime.h>
#include <cuda_fp16.h>
#include <cstdint>

// ---------------- problem constants (fixed by setup_inputs) ----------------
#define B_SZ   2
#define N_TOK  32768
#define DIM    512
#define HEADS  8
#define DH     64
#define NGRAPH 32
#define QKV3   1536
#define M_ROWS (B_SZ * N_TOK)          // 65536
#define KDIM   512
#define TILEMAX 288                    // max token-tiles per batch

// ---------------- device scratch (static; no allocations allowed) ----------
__device__ __half g_a_hi[(size_t)M_ROWS * KDIM];
__device__ __half g_b1_hi[QKV3 * KDIM];
__device__ __half g_b2_hi[DIM * KDIM];
__device__ __half g_q_hi[((size_t)M_ROWS + 128) * DIM];   // +128 slack rows
__device__ __half g_k_hi[(size_t)M_ROWS * DIM];
__device__ __half g_k_lo[(size_t)M_ROWS * DIM];
__device__ __half g_v_hi[(size_t)M_ROWS * DIM];
__device__ __half g_v_lo[(size_t)M_ROWS * DIM];
__device__ __half g_attn_hi[(size_t)M_ROWS * DIM];
__device__ __half g_ktvT_hi[B_SZ * HEADS * NGRAPH * DH * DH];
__device__ __half g_ktvT_lo[B_SZ * HEADS * NGRAPH * DH * DH];
__device__ int    g_sizes[NGRAPH];
__device__ int    g_off [NGRAPH + 1];
__device__ int    g_tile_g[TILEMAX];
__device__ int    g_tile_tok0[TILEMAX];
__device__ int    g_tile_nval[TILEMAX];

// ---------------- helpers ---------------------------------------------------
__device__ __forceinline__ uint32_t smem_u32(const void* p) {
    uint32_t a;
    asm("{ .reg .u64 t; cvta.to.shared.u64 t, %1; cvt.u32.u64 %0, t; }"
        : "=r"(a) : "l"(p));
    return a;
}
__device__ __forceinline__ void mma16816(float* d, const uint32_t* a, const uint32_t* b) {
    asm volatile(
        "mma.sync.aligned.m16n8k16.row.col.f32.f16.f16.f32 "
        "{%0,%1,%2,%3}, {%4,%5,%6,%7}, {%8,%9}, {%0,%1,%2,%3};"
        : "+f"(d[0]), "+f"(d[1]), "+f"(d[2]), "+f"(d[3])
        : "r"(a[0]), "r"(a[1]), "r"(a[2]), "r"(a[3]), "r"(b[0]), "r"(b[1]));
}
#define LDMX4(r, addr) \
    asm volatile("ldmatrix.sync.aligned.m8n8.x4.shared.b16 {%0,%1,%2,%3}, [%4];" \
                 : "=r"((r)[0]), "=r"((r)[1]), "=r"((r)[2]), "=r"((r)[3]) : "r"(addr))
#define LDMX4T(r, addr) \
    asm volatile("ldmatrix.sync.aligned.m8n8.x4.trans.shared.b16 {%0,%1,%2,%3}, [%4];" \
                 : "=r"((r)[0]), "=r"((r)[1]), "=r"((r)[2]), "=r"((r)[3]) : "r"(addr))
#define CPA16(s, gp) \
    asm volatile("cp.async.cg.shared.global [%0], [%1], 16;" :: "r"(s), "l"(gp))

// ---------------- hist + tile tables ----------------------------------------
__global__ void hist_kernel(const int* __restrict__ batch) {
    __shared__ int cnt[NGRAPH];
    int tid = threadIdx.x;
    if (tid < NGRAPH) cnt[tid] = 0;
    __syncthreads();
    for (int i = tid; i < N_TOK; i += 256) atomicAdd(&cnt[batch[i]], 1);
    __syncthreads();
    if (tid == 0) {
        int off = 0;
        for (int g = 0; g < NGRAPH; g++) {
            g_off[g] = off; g_sizes[g] = cnt[g]; off += cnt[g];
        }
        g_off[NGRAPH] = off;
        int t = 0;
        for (int g = 0; g < NGRAPH; g++) {
            int S = g_sizes[g];
            for (int i = 0; i < S; i += 128) {
                g_tile_g[t] = g;
                g_tile_tok0[t] = g_off[g] + i;
                g_tile_nval[t] = (S - i < 128) ? (S - i) : 128;
                t++;
            }
        }
        for (; t < TILEMAX; t++) g_tile_nval[t] = 0;
    }
}

__device__ __forceinline__ void split2(float f0, float f1, ushort2& uh, ushort2& ul) {
    __half h0 = __float2half_rn(f0), h1 = __float2half_rn(f1);
    __half l0 = __float2half_rn(f0 - __half2float(h0));
    __half l1 = __float2half_rn(f1 - __half2float(h1));
    uh = make_ushort2(__half_as_ushort(h0), __half_as_ushort(h1));
    ul = make_ushort2(__half_as_ushort(l0), __half_as_ushort(l1));
}
__device__ __forceinline__ ushort4 round4(float4 v) {
    ushort4 r;
    r.x = __half_as_ushort(__float2half_rn(v.x));
    r.y = __half_as_ushort(__float2half_rn(v.y));
    r.z = __half_as_ushort(__float2half_rn(v.z));
    r.w = __half_as_ushort(__float2half_rn(v.w));
    return r;
}

// fp32 -> fp16 round, x4
__global__ void conv_round_kernel(const float* __restrict__ src,
                                  __half* __restrict__ dst, long n4) {
    long i = (long)blockIdx.x * blockDim.x + threadIdx.x;
    long stride = (long)gridDim.x * blockDim.x;
    for (; i < n4; i += stride)
        ((ushort4*)dst)[i] = round4(((const float4*)src)[i]);
}

// weights: fp16 rounding, one launch
__global__ void conv_w_kernel(const float* __restrict__ w1,
                              const float* __restrict__ w2) {
    const long n1 = (long)QKV3 * KDIM / 4;
    const long n2 = (long)DIM * KDIM / 4;
    long i = (long)blockIdx.x * blockDim.x + threadIdx.x;
    long stride = (long)gridDim.x * blockDim.x;
    for (; i < n1 + n2; i += stride) {
        if (i < n1) ((ushort4*)g_b1_hi)[i]      = round4(((const float4*)w1)[i]);
        else        ((ushort4*)g_b2_hi)[i - n1] = round4(((const float4*)w2)[i - n1]);
    }
}

#define TEN_BYTES (128 * 144)

__device__ __forceinline__ void issue_slab(uint32_t sdst, const __half* g,
                                           int k0, int tid) {
#pragma unroll
    for (int t = 0; t < 4; t++) {
        int id  = tid + t * 256;
        int row = id >> 3, col = id & 7;
        CPA16(sdst + row * 144 + col * 16, g + (size_t)row * KDIM + k0 + col * 8);
    }
}

// ---------------- GEMM1: qkv = x16 @ w16^T (1-term fp16, 3-stage ring) ------
// R11 config: CTA 128x128, warp 32x64, 2 CTAs/SM. (R12's 128x256 falsified.)
// epilogue: q scale->hi only, k LN(ln1)->split, v LN(ln2)->split
#define QK_SMEM (3 * 2 * TEN_BYTES)   // 110592 -> 2 CTAs/SM

__global__ __launch_bounds__(256, 2)
void qkv_gemm_kernel(const __half* __restrict__ Ah, const __half* __restrict__ Bh,
                     const int* __restrict__ batch,
                     const float* __restrict__ ln1w, const float* __restrict__ ln1b,
                     const float* __restrict__ ln2w, const float* __restrict__ ln2b) {
    extern __shared__ __align__(16) char smem[];
    uint32_t sb = smem_u32(smem);
    int tid = threadIdx.x, wid = tid >> 5, lane = tid & 31;
    int warpM = (wid & 3) * 32;
    int warpN = (wid >> 2) * 64;
    int g = lane >> 2, c2 = lane & 3;

    uint32_t aoff = (lane & 15) * 144 + (lane >> 4) * 16;
    uint32_t boff = ((lane & 7) + ((lane >> 4) << 3)) * 144 + ((lane >> 3) & 1) * 16;

    const __half* pAh = Ah + (size_t)blockIdx.y * 128 * KDIM;
    const __half* pBh = Bh + (size_t)blockIdx.x * 128 * KDIM;

#define QST(s, t) (sb + ((s) * 2 + (t)) * TEN_BYTES)
#define Q_ISSUE(s, k0)                            \
    do {                                          \
        issue_slab(QST(s, 0), pAh, (k0), tid);    \
        issue_slab(QST(s, 1), pBh, (k0), tid);    \
        asm volatile("cp.async.commit_group;");   \
    } while (0)

    Q_ISSUE(0, 0);
    Q_ISSUE(1, 64);

    float acc[2][8][4];
#pragma unroll
    for (int i = 0; i < 2; i++)
#pragma unroll
        for (int j = 0; j < 8; j++)
#pragma unroll
            for (int k = 0; k < 4; k++) acc[i][j][k] = 0.0f;

    for (int it = 0; it < 8; it++) {
        int s = it % 3;
        if (it < 7) asm volatile("cp.async.wait_group 1;");
        else        asm volatile("cp.async.wait_group 0;");
        __syncthreads();   // single barrier: frees stage (it+2)%3 too
        uint32_t aA0 = QST(s, 0) + warpM * 144 + aoff;
        uint32_t aB0 = QST(s, 1) + warpN * 144 + boff;
#pragma unroll
        for (int kk = 0; kk < 4; kk++) {
            int ko = kk * 32;
            uint32_t ah[2][4], bf[4][4];
            LDMX4(ah[0], aA0 + ko); LDMX4(ah[1], aA0 + 16 * 144 + ko);
#pragma unroll
            for (int p = 0; p < 4; p++) LDMX4(bf[p], aB0 + p * 16 * 144 + ko);
#pragma unroll
            for (int mt = 0; mt < 2; mt++)
#pragma unroll
                for (int nt = 0; nt < 8; nt++)
                    mma16816(acc[mt][nt], ah[mt], &bf[nt >> 1][(nt & 1) * 2]);
        }
        if (it + 2 < 8) Q_ISSUE((it + 2) % 3, (it + 2) * 64);
    }

    // epilogue: q scale (hi only) / k,v LN+split
    int mode = blockIdx.x >> 2;          // 0 q, 1 k, 2 v
    const float* lw = (mode == 1) ? ln1w : ln2w;
    const float* lb = (mode == 1) ? ln1b : ln2b;
    __half* dh = (mode == 0) ? g_q_hi : (mode == 1) ? g_k_hi : g_v_hi;
    __half* dl = (mode == 1) ? g_k_lo : g_v_lo;
    int colbase = blockIdx.x * 128 - mode * 512 + warpN;   // 0..511 in buffer
#pragma unroll
    for (int mt = 0; mt < 2; mt++) {
#pragma unroll
        for (int hf = 0; hf < 2; hf++) {
            size_t m = (size_t)blockIdx.y * 128 + warpM + mt * 16 + g + hf * 8;
            float v[16];
#pragma unroll
            for (int nt = 0; nt < 8; nt++) {
                v[nt * 2]     = acc[mt][nt][hf * 2];
                v[nt * 2 + 1] = acc[mt][nt][hf * 2 + 1];
            }
            size_t base = m * DIM + colbase + c2 * 2;
            if (mode == 0) {
                int n = (int)(m & (N_TOK - 1));
                float sc = 1.0f / (float)g_sizes[batch[n]];
#pragma unroll
                for (int nt = 0; nt < 8; nt++) {
                    ushort2 uh = make_ushort2(
                        __half_as_ushort(__float2half_rn(v[nt * 2] * sc)),
                        __half_as_ushort(__float2half_rn(v[nt * 2 + 1] * sc)));
                    *(ushort2*)((unsigned short*)dh + base + nt * 8) = uh;
                }
            } else {
                float s = 0.f, s2 = 0.f;
#pragma unroll
                for (int k = 0; k < 16; k++) { s += v[k]; s2 += v[k] * v[k]; }
                s  += __shfl_xor_sync(0xffffffffu, s, 1);
                s  += __shfl_xor_sync(0xffffffffu, s, 2);
                s2 += __shfl_xor_sync(0xffffffffu, s2, 1);
                s2 += __shfl_xor_sync(0xffffffffu, s2, 2);
                float mu = s * (1.0f / 64.0f);
                float var = s2 * (1.0f / 64.0f) - mu * mu;
                float rs = rsqrtf(var + 1e-6f);
#pragma unroll
                for (int nt = 0; nt < 8; nt++) {
                    int cl = ((warpN + nt * 8 + c2 * 2) & 63); // head-local
                    float f0 = (v[nt * 2]     - mu) * rs * lw[cl]     + lb[cl];
                    float f1 = (v[nt * 2 + 1] - mu) * rs * lw[cl + 1] + lb[cl + 1];
                    ushort2 uh, ul;
                    split2(f0, f1, uh, ul);
                    *(ushort2*)((unsigned short*)dh + base + nt * 8) = uh;
                    *(ushort2*)((unsigned short*)dl + base + nt * 8) = ul;
                }
            }
        }
    }
#undef QST
#undef Q_ISSUE
}

// ---------------- GEMM2: out = attn_hi @ w_out^T + bias (1-term, 3-stage) ---
#define OG_SMEM (3 * 2 * TEN_BYTES)   // 110592 -> 2 CTAs/SM

__global__ __launch_bounds__(256, 2)
void out_gemm_kernel(const __half* __restrict__ Ah, const __half* __restrict__ Bh,
                     float* __restrict__ C, const float* __restrict__ bias) {
    extern __shared__ __align__(16) char smem[];
    uint32_t sb = smem_u32(smem);
    int tid = threadIdx.x, wid = tid >> 5, lane = tid & 31;
    int warpM = (wid & 3) * 32;
    int warpN = (wid >> 2) * 64;
    int g = lane >> 2, c2 = lane & 3;

    uint32_t aoff = (lane & 15) * 144 + (lane >> 4) * 16;
    uint32_t boff = ((lane & 7) + ((lane >> 4) << 3)) * 144 + ((lane >> 3) & 1) * 16;

    const __half* pAh = Ah + (size_t)blockIdx.y * 128 * KDIM;
    const __half* pBh = Bh + (size_t)blockIdx.x * 128 * KDIM;

#define OST(s, t) (sb + ((s) * 2 + (t)) * TEN_BYTES)
#define O_ISSUE(s, k0)                            \
    do {                                          \
        issue_slab(OST(s, 0), pAh, (k0), tid);    \
        issue_slab(OST(s, 1), pBh, (k0), tid);    \
        asm volatile("cp.async.commit_group;");   \
    } while (0)

    O_ISSUE(0, 0);
    O_ISSUE(1, 64);

    float acc[2][8][4];
#pragma unroll
    for (int i = 0; i < 2; i++)
#pragma unroll
        for (int j = 0; j < 8; j++)
#pragma unroll
            for (int k = 0; k < 4; k++) acc[i][j][k] = 0.0f;

    for (int it = 0; it < 8; it++) {
        int s = it % 3;
        if (it < 7) asm volatile("cp.async.wait_group 1;");
        else        asm volatile("cp.async.wait_group 0;");
        __syncthreads();   // single barrier (3-stage ring)
        uint32_t aA0 = OST(s, 0) + warpM * 144 + aoff;
        uint32_t aB0 = OST(s, 1) + warpN * 144 + boff;
#pragma unroll
        for (int kk = 0; kk < 4; kk++) {
            int ko = kk * 32;
            uint32_t ah[2][4], bf[4][4];
            LDMX4(ah[0], aA0 + ko); LDMX4(ah[1], aA0 + 16 * 144 + ko);
#pragma unroll
            for (int p = 0; p < 4; p++) LDMX4(bf[p], aB0 + p * 16 * 144 + ko);
#pragma unroll
            for (int mt = 0; mt < 2; mt++)
#pragma unroll
                for (int nt = 0; nt < 8; nt++)
                    mma16816(acc[mt][nt], ah[mt], &bf[nt >> 1][(nt & 1) * 2]);
        }
        if (it + 2 < 8) O_ISSUE((it + 2) % 3, (it + 2) * 64);
    }

#pragma unroll
    for (int mt = 0; mt < 2; mt++) {
        size_t m0 = (size_t)blockIdx.y * 128 + warpM + mt * 16 + g;
#pragma unroll
        for (int nt = 0; nt < 8; nt++) {
            int nc = blockIdx.x * 128 + warpN + nt * 8 + c2 * 2;
            float b0 = bias[nc], b1 = bias[nc + 1];
            *(float2*)(C + m0 * DIM + nc) =
                make_float2(acc[mt][nt][0] + b0, acc[mt][nt][1] + b1);
            *(float2*)(C + (m0 + 8) * DIM + nc) =
                make_float2(acc[mt][nt][2] + b0, acc[mt][nt][3] + b1);
        }
    }
#undef OST
#undef O_ISSUE
}

// ---------------- ktvT[b,h,g] (tensor, 3-term, ldmatrix.trans) --------------
#define KT_SLAB  (64 * 144)
#define KT_STAGE (4 * KT_SLAB)
#define KT_SMEM  (2 * KT_STAGE)      // 73728

__global__ __launch_bounds__(128, 2)
void ktvmma_kernel() {
    int gseg = blockIdx.x & 31;
    int h = (blockIdx.x >> 5) & 7;
    int b = blockIdx.x >> 8;
    int s0 = g_off[gseg], s1 = g_off[gseg + 1];
    int NCH = (s1 - s0 + 63) >> 6;
    if (NCH <= 0) NCH = 1;

    extern __shared__ __align__(16) char smem[];
    uint32_t sb = smem_u32(smem);
    int tid = threadIdx.x, wid = tid >> 5, lane = tid & 31;
    int lg = lane >> 2, c2 = lane & 3;

#define KT_ISSUE(st, c)                                                        \
    do {                                                                       \
        int t0 = s0 + (c) * 64;                                                \
        uint32_t base = sb + (st) * KT_STAGE;                                  \
        char* cbase = smem + (st) * KT_STAGE;                                  \
        _Pragma("unroll")                                                      \
        for (int i = 0; i < 4; i++) {                                          \
            int id = tid + i * 128;                                            \
            int row = id >> 3, ch = id & 7;                                    \
            int tok = t0 + row;                                                \
            uint32_t so = row * 144 + ch * 16;                                 \
            if (tok < s1) {                                                    \
                size_t go = ((size_t)b * N_TOK + tok) * DIM + h * DH + ch * 8; \
                CPA16(base + 0 * KT_SLAB + so, g_k_hi + go);                   \
                CPA16(base + 1 * KT_SLAB + so, g_k_lo + go);                   \
                CPA16(base + 2 * KT_SLAB + so, g_v_hi + go);                   \
                CPA16(base + 3 * KT_SLAB + so, g_v_lo + go);                   \
            } else {                                                           \
                uint4 z = make_uint4(0, 0, 0, 0);                              \
                *(uint4*)(cbase + 0 * KT_SLAB + so) = z;                       \
                *(uint4*)(cbase + 1 * KT_SLAB + so) = z;                       \
                *(uint4*)(cbase + 2 * KT_SLAB + so) = z;                       \
                *(uint4*)(cbase + 3 * KT_SLAB + so) = z;                       \
            }                                                                  \
        }                                                                      \
        asm volatile("cp.async.commit_group;");                                \
    } while (0)

    KT_ISSUE(0, 0);
    if (NCH > 1) KT_ISSUE(1, 1);

    uint32_t aoffT = ((lane & 7) + (lane >> 4) * 8) * 144 + ((lane >> 3) & 1) * 16;
    uint32_t boffT = ((lane & 7) + ((lane >> 3) & 1) * 8) * 144 + (lane >> 4) * 16;

    float acc[8][4];
#pragma unroll
    for (int j = 0; j < 8; j++)
#pragma unroll
        for (int k = 0; k < 4; k++) acc[j][k] = 0.0f;

    for (int c = 0; c < NCH; c++) {
        int st = c & 1;
        if (c + 2 <= NCH) asm volatile("cp.async.wait_group 1;");
        else              asm volatile("cp.async.wait_group 0;");
        __syncthreads();
        uint32_t base = sb + st * KT_STAGE;
        uint32_t aKh = base + 0 * KT_SLAB + boffT;
        uint32_t aKl = base + 1 * KT_SLAB + boffT;
        uint32_t aVh = base + 2 * KT_SLAB + wid * 32 + aoffT;
        uint32_t aVl = base + 3 * KT_SLAB + wid * 32 + aoffT;
#pragma unroll
        for (int kk = 0; kk < 4; kk++) {
            int ko = kk * (16 * 144);
            uint32_t vh[4], vl[4], kh[4][4], kl[4][4];
            LDMX4T(vh, aVh + ko);
            LDMX4T(vl, aVl + ko);
#pragma unroll
            for (int nb = 0; nb < 4; nb++) {
                LDMX4T(kh[nb], aKh + nb * 32 + ko);
                LDMX4T(kl[nb], aKl + nb * 32 + ko);
            }
#pragma unroll
            for (int nt = 0; nt < 8; nt++) {
                mma16816(acc[nt], vh, &kh[nt >> 1][(nt & 1) * 2]);
                mma16816(acc[nt], vl, &kh[nt >> 1][(nt & 1) * 2]);
                mma16816(acc[nt], vh, &kl[nt >> 1][(nt & 1) * 2]);
            }
        }
        __syncthreads();
        if (c + 2 < NCH) KT_ISSUE(st, c + 2);
    }

    size_t kb = (size_t)blockIdx.x * (DH * DH);
    int r0 = wid * 16 + lg;
#pragma unroll
    for (int nt = 0; nt < 8; nt++) {
        int cidx = nt * 8 + c2 * 2;
        ushort2 uh, ul;
        split2(acc[nt][0], acc[nt][1], uh, ul);
        *(ushort2*)((unsigned short*)g_ktvT_hi + kb + (size_t)r0 * DH + cidx) = uh;
        *(ushort2*)((unsigned short*)g_ktvT_lo + kb + (size_t)r0 * DH + cidx) = ul;
        split2(acc[nt][2], acc[nt][3], uh, ul);
        *(ushort2*)((unsigned short*)g_ktvT_hi + kb + (size_t)(r0 + 8) * DH + cidx) = uh;
        *(ushort2*)((unsigned short*)g_ktvT_lo + kb + (size_t)(r0 + 8) * DH + cidx) = ul;
    }
#undef KT_ISSUE
}

// ---------------- attn tile = qh @ (Th + Tl) (tensor, 2-term) ---------------
#define AP_QSLAB (128 * 144)
#define AP_TSLAB (64 * 144)
#define AP_SMEM  (AP_QSLAB + 2 * AP_TSLAB)   // 36864

__global__ __launch_bounds__(256, 2)
void applymma_kernel() {
    int h = blockIdx.x, ti = blockIdx.y, b = blockIdx.z;
    int nval = g_tile_nval[ti];
    if (nval == 0) return;
    int gseg = g_tile_g[ti];
    int tok0 = g_tile_tok0[ti];

    extern __shared__ __align__(16) char smem[];
    uint32_t sb = smem_u32(smem);
    uint32_t sQh = sb;
    uint32_t sTh = sb + AP_QSLAB, sTl = sTh + AP_TSLAB;

    int tid = threadIdx.x, wid = tid >> 5, lane = tid & 31;
    int warpM = (wid & 3) * 32;
    int warpN = (wid >> 2) * 32;
    int g = lane >> 2, c2 = lane & 3;

    {
        size_t qrow0 = (size_t)b * N_TOK + tok0;
#pragma unroll
        for (int t = 0; t < 4; t++) {
            int id = tid + t * 256;          // 0..1023
            int row = id >> 3, ch = id & 7;
            size_t go = (qrow0 + row) * DIM + h * DH + ch * 8;
            CPA16(sQh + row * 144 + ch * 16, (const __half*)g_q_hi + go);
        }
        size_t kbase = ((size_t)((b * HEADS + h) * NGRAPH + gseg)) * DH * DH;
#pragma unroll
        for (int t = 0; t < 2; t++) {
            int id = tid + t * 256;          // 0..511
            int row = id >> 3, ch = id & 7;
            size_t ko = kbase + (size_t)row * DH + ch * 8;
            CPA16(sTh + row * 144 + ch * 16, (const __half*)g_ktvT_hi + ko);
            CPA16(sTl + row * 144 + ch * 16, (const __half*)g_ktvT_lo + ko);
        }
        asm volatile("cp.async.commit_group;");
        asm volatile("cp.async.wait_group 0;");
        __syncthreads();
    }

    uint32_t aoff = (lane & 15) * 144 + (lane >> 4) * 16;
    uint32_t boff = ((lane & 7) + ((lane >> 4) << 3)) * 144 + ((lane >> 3) & 1) * 16;

    float acc[2][4][4];
#pragma unroll
    for (int i = 0; i < 2; i++)
#pragma unroll
        for (int j = 0; j < 4; j++)
#pragma unroll
            for (int k = 0; k < 4; k++) acc[i][j][k] = 0.0f;

    uint32_t aQh = sQh + warpM * 144 + aoff;
    uint32_t aTh = sTh + warpN * 144 + boff;
    uint32_t aTl = sTl + warpN * 144 + boff;

#pragma unroll
    for (int kk = 0; kk < 4; kk++) {
        int ko = kk * 32;
        uint32_t qh[2][4], bh[2][4], bl[2][4];
        LDMX4(qh[0], aQh + ko); LDMX4(qh[1], aQh + 16 * 144 + ko);
        LDMX4(bh[0], aTh + ko); LDMX4(bh[1], aTh + 16 * 144 + ko);
        LDMX4(bl[0], aTl + ko); LDMX4(bl[1], aTl + 16 * 144 + ko);
#pragma unroll
        for (int mt = 0; mt < 2; mt++)
#pragma unroll
            for (int nt = 0; nt < 4; nt++) {
                const uint32_t* bph = &bh[nt >> 1][(nt & 1) * 2];
                const uint32_t* bpl = &bl[nt >> 1][(nt & 1) * 2];
                mma16816(acc[mt][nt], qh[mt], bph);
                mma16816(acc[mt][nt], qh[mt], bpl);
            }
    }

    // masked epilogue -> attn hi only
#pragma unroll
    for (int mt = 0; mt < 2; mt++) {
#pragma unroll
        for (int hf = 0; hf < 2; hf++) {
            int r = warpM + mt * 16 + g + hf * 8;
            if (r < nval) {
                size_t base = ((size_t)b * N_TOK + tok0 + r) * DIM + h * DH + warpN + c2 * 2;
#pragma unroll
                for (int nt = 0; nt < 4; nt++) {
                    float f0 = acc[mt][nt][hf * 2], f1 = acc[mt][nt][hf * 2 + 1];
                    ushort2 uh = make_ushort2(
                        __half_as_ushort(__float2half_rn(f0)),
                        __half_as_ushort(__float2half_rn(f1)));
                    *(ushort2*)((unsigned short*)g_attn_hi + base + nt * 8) = uh;
                }
            }
        }
    }
}

// ---------------- launch ----------------------------------------------------
extern "C" void kernel_launch(void* const* d_in, const int* in_sizes, int n_in,
                              void* d_out, int out_size) {
    const float* x     = (const float*)d_in[0];
    const float* w_qkv = (const float*)d_in[1];
    const float* ln1w  = (const float*)d_in[2];
    const float* ln1b  = (const float*)d_in[3];
    const float* ln2w  = (const float*)d_in[4];
    const float* ln2b  = (const float*)d_in[5];
    const float* w_out = (const float*)d_in[6];
    const float* b_out = (const float*)d_in[7];
    const int*   batch = (const int*)d_in[8];
    float* out = (float*)d_out;

    __half *ah_p, *b1h_p, *b2h_p, *ath_p;
    cudaGetSymbolAddress((void**)&ah_p,  g_a_hi);
    cudaGetSymbolAddress((void**)&b1h_p, g_b1_hi);
    cudaGetSymbolAddress((void**)&b2h_p, g_b2_hi);
    cudaGetSymbolAddress((void**)&ath_p, g_attn_hi);

    cudaFuncSetAttribute(qkv_gemm_kernel, cudaFuncAttributeMaxDynamicSharedMemorySize, QK_SMEM);
    cudaFuncSetAttribute(out_gemm_kernel, cudaFuncAttributeMaxDynamicSharedMemorySize, OG_SMEM);
    cudaFuncSetAttribute(ktvmma_kernel,   cudaFuncAttributeMaxDynamicSharedMemorySize, KT_SMEM);
    cudaFuncSetAttribute(applymma_kernel, cudaFuncAttributeMaxDynamicSharedMemorySize, AP_SMEM);

    // 0) segment offsets + tile tables
    hist_kernel<<<1, 256>>>(batch);

    // 1) conversions
    conv_round_kernel<<<4096, 256>>>(x, ah_p, (long)M_ROWS * KDIM / 4);
    conv_w_kernel<<<1024, 256>>>(w_qkv, w_out);

    // 2) qkv GEMM (1-term fp16, 3-stage, R11 tile config) + fused epilogue
    qkv_gemm_kernel<<<dim3(QKV3 / 128, M_ROWS / 128), 256, QK_SMEM>>>(
        ah_p, b1h_p, batch, ln1w, ln1b, ln2w, ln2b);

    // 3) ktvT per (b,h,g) (tensor, 3-term)
    ktvmma_kernel<<<B_SZ * HEADS * NGRAPH, 128, KT_SMEM>>>();

    // 4) attn = qh @ (Th+Tl) (tensor, 2-term, masked ragged tiles)
    applymma_kernel<<<dim3(HEADS, TILEMAX, B_SZ), 256, AP_SMEM>>>();

    // 5) out = attn_hi @ w_outT + bias (1-term, 3-stage)
    out_gemm_kernel<<<dim3(DIM / 128, M_ROWS / 128), 256, OG_SMEM>>>(
        ath_p, b2h_p, out, b_out);
}

// round 14
// speedup vs baseline: 1.2077x; 1.0586x over previous
#include <cuda_runtime.h>
#include <cuda_fp16.h>
#include <cstdint>

// ---------------- problem constants (fixed by setup_inputs) ----------------
#define B_SZ   2
#define N_TOK  32768
#define DIM    512
#define HEADS  8
#define DH     64
#define NGRAPH 32
#define QKV3   1536
#define M_ROWS (B_SZ * N_TOK)          // 65536
#define KDIM   512
#define TILEMAX 288                    // max token-tiles per batch

// ---------------- device scratch (static; no allocations allowed) ----------
__device__ __half g_a_hi[(size_t)M_ROWS * KDIM];
__device__ __half g_b1_hi[QKV3 * KDIM];
__device__ __half g_b2_hi[DIM * KDIM];
__device__ __half g_q_hi[((size_t)M_ROWS + 128) * DIM];   // +128 slack rows
__device__ __half g_k_hi[(size_t)M_ROWS * DIM];
__device__ __half g_k_lo[(size_t)M_ROWS * DIM];
__device__ __half g_v_hi[(size_t)M_ROWS * DIM];
__device__ __half g_attn_hi[(size_t)M_ROWS * DIM];
__device__ __half g_ktvT_hi[B_SZ * HEADS * NGRAPH * DH * DH];
__device__ __half g_ktvT_lo[B_SZ * HEADS * NGRAPH * DH * DH];
__device__ int    g_sizes[NGRAPH];
__device__ int    g_off [NGRAPH + 1];
__device__ int    g_tile_g[TILEMAX];
__device__ int    g_tile_tok0[TILEMAX];
__device__ int    g_tile_nval[TILEMAX];

// ---------------- helpers ---------------------------------------------------
__device__ __forceinline__ uint32_t smem_u32(const void* p) {
    uint32_t a;
    asm("{ .reg .u64 t; cvta.to.shared.u64 t, %1; cvt.u32.u64 %0, t; }"
        : "=r"(a) : "l"(p));
    return a;
}
__device__ __forceinline__ void mma16816(float* d, const uint32_t* a, const uint32_t* b) {
    asm volatile(
        "mma.sync.aligned.m16n8k16.row.col.f32.f16.f16.f32 "
        "{%0,%1,%2,%3}, {%4,%5,%6,%7}, {%8,%9}, {%0,%1,%2,%3};"
        : "+f"(d[0]), "+f"(d[1]), "+f"(d[2]), "+f"(d[3])
        : "r"(a[0]), "r"(a[1]), "r"(a[2]), "r"(a[3]), "r"(b[0]), "r"(b[1]));
}
#define LDMX4(r, addr) \
    asm volatile("ldmatrix.sync.aligned.m8n8.x4.shared.b16 {%0,%1,%2,%3}, [%4];" \
                 : "=r"((r)[0]), "=r"((r)[1]), "=r"((r)[2]), "=r"((r)[3]) : "r"(addr))
#define LDMX4T(r, addr) \
    asm volatile("ldmatrix.sync.aligned.m8n8.x4.trans.shared.b16 {%0,%1,%2,%3}, [%4];" \
                 : "=r"((r)[0]), "=r"((r)[1]), "=r"((r)[2]), "=r"((r)[3]) : "r"(addr))
#define CPA16(s, gp) \
    asm volatile("cp.async.cg.shared.global [%0], [%1], 16;" :: "r"(s), "l"(gp))

// ---------------- hist + tile tables ----------------------------------------
__global__ void hist_kernel(const int* __restrict__ batch) {
    __shared__ int cnt[NGRAPH];
    int tid = threadIdx.x;
    if (tid < NGRAPH) cnt[tid] = 0;
    __syncthreads();
    for (int i = tid; i < N_TOK; i += 256) atomicAdd(&cnt[batch[i]], 1);
    __syncthreads();
    if (tid == 0) {
        int off = 0;
        for (int g = 0; g < NGRAPH; g++) {
            g_off[g] = off; g_sizes[g] = cnt[g]; off += cnt[g];
        }
        g_off[NGRAPH] = off;
        int t = 0;
        for (int g = 0; g < NGRAPH; g++) {
            int S = g_sizes[g];
            for (int i = 0; i < S; i += 128) {
                g_tile_g[t] = g;
                g_tile_tok0[t] = g_off[g] + i;
                g_tile_nval[t] = (S - i < 128) ? (S - i) : 128;
                t++;
            }
        }
        for (; t < TILEMAX; t++) g_tile_nval[t] = 0;
    }
}

__device__ __forceinline__ void split2(float f0, float f1, ushort2& uh, ushort2& ul) {
    __half h0 = __float2half_rn(f0), h1 = __float2half_rn(f1);
    __half l0 = __float2half_rn(f0 - __half2float(h0));
    __half l1 = __float2half_rn(f1 - __half2float(h1));
    uh = make_ushort2(__half_as_ushort(h0), __half_as_ushort(h1));
    ul = make_ushort2(__half_as_ushort(l0), __half_as_ushort(l1));
}
__device__ __forceinline__ ushort4 round4(float4 v) {
    ushort4 r;
    r.x = __half_as_ushort(__float2half_rn(v.x));
    r.y = __half_as_ushort(__float2half_rn(v.y));
    r.z = __half_as_ushort(__float2half_rn(v.z));
    r.w = __half_as_ushort(__float2half_rn(v.w));
    return r;
}

// fp32 -> fp16 round, x4
__global__ void conv_round_kernel(const float* __restrict__ src,
                                  __half* __restrict__ dst, long n4) {
    long i = (long)blockIdx.x * blockDim.x + threadIdx.x;
    long stride = (long)gridDim.x * blockDim.x;
    for (; i < n4; i += stride)
        ((ushort4*)dst)[i] = round4(((const float4*)src)[i]);
}

// weights: fp16 rounding, one launch
__global__ void conv_w_kernel(const float* __restrict__ w1,
                              const float* __restrict__ w2) {
    const long n1 = (long)QKV3 * KDIM / 4;
    const long n2 = (long)DIM * KDIM / 4;
    long i = (long)blockIdx.x * blockDim.x + threadIdx.x;
    long stride = (long)gridDim.x * blockDim.x;
    for (; i < n1 + n2; i += stride) {
        if (i < n1) ((ushort4*)g_b1_hi)[i]      = round4(((const float4*)w1)[i]);
        else        ((ushort4*)g_b2_hi)[i - n1] = round4(((const float4*)w2)[i - n1]);
    }
}

#define TEN_BYTES (128 * 144)

__device__ __forceinline__ void issue_slab(uint32_t sdst, const __half* g,
                                           int k0, int tid) {
#pragma unroll
    for (int t = 0; t < 4; t++) {
        int id  = tid + t * 256;
        int row = id >> 3, col = id & 7;
        CPA16(sdst + row * 144 + col * 16, g + (size_t)row * KDIM + k0 + col * 8);
    }
}

// ---------------- GEMM1: qkv = x16 @ w16^T (1-term fp16, 3-stage ring) ------
// epilogue: q scale->hi, k LN(ln1)->hi/lo, v LN(ln2)->hi only
#define QK_SMEM (3 * 2 * TEN_BYTES)   // 110592 -> 2 CTAs/SM

__global__ __launch_bounds__(256, 2)
void qkv_gemm_kernel(const __half* __restrict__ Ah, const __half* __restrict__ Bh,
                     const int* __restrict__ batch,
                     const float* __restrict__ ln1w, const float* __restrict__ ln1b,
                     const float* __restrict__ ln2w, const float* __restrict__ ln2b) {
    extern __shared__ __align__(16) char smem[];
    uint32_t sb = smem_u32(smem);
    int tid = threadIdx.x, wid = tid >> 5, lane = tid & 31;
    int warpM = (wid & 3) * 32;
    int warpN = (wid >> 2) * 64;
    int g = lane >> 2, c2 = lane & 3;

    uint32_t aoff = (lane & 15) * 144 + (lane >> 4) * 16;
    uint32_t boff = ((lane & 7) + ((lane >> 4) << 3)) * 144 + ((lane >> 3) & 1) * 16;

    const __half* pAh = Ah + (size_t)blockIdx.y * 128 * KDIM;
    const __half* pBh = Bh + (size_t)blockIdx.x * 128 * KDIM;

#define QST(s, t) (sb + ((s) * 2 + (t)) * TEN_BYTES)
#define Q_ISSUE(s, k0)                            \
    do {                                          \
        issue_slab(QST(s, 0), pAh, (k0), tid);    \
        issue_slab(QST(s, 1), pBh, (k0), tid);    \
        asm volatile("cp.async.commit_group;");   \
    } while (0)

    Q_ISSUE(0, 0);
    Q_ISSUE(1, 64);

    float acc[2][8][4];
#pragma unroll
    for (int i = 0; i < 2; i++)
#pragma unroll
        for (int j = 0; j < 8; j++)
#pragma unroll
            for (int k = 0; k < 4; k++) acc[i][j][k] = 0.0f;

    for (int it = 0; it < 8; it++) {
        int s = it % 3;
        if (it < 7) asm volatile("cp.async.wait_group 1;");
        else        asm volatile("cp.async.wait_group 0;");
        __syncthreads();   // single barrier: frees stage (it+2)%3 too
        uint32_t aA0 = QST(s, 0) + warpM * 144 + aoff;
        uint32_t aB0 = QST(s, 1) + warpN * 144 + boff;
#pragma unroll
        for (int kk = 0; kk < 4; kk++) {
            int ko = kk * 32;
            uint32_t ah[2][4], bf[4][4];
            LDMX4(ah[0], aA0 + ko); LDMX4(ah[1], aA0 + 16 * 144 + ko);
#pragma unroll
            for (int p = 0; p < 4; p++) LDMX4(bf[p], aB0 + p * 16 * 144 + ko);
#pragma unroll
            for (int mt = 0; mt < 2; mt++)
#pragma unroll
                for (int nt = 0; nt < 8; nt++)
                    mma16816(acc[mt][nt], ah[mt], &bf[nt >> 1][(nt & 1) * 2]);
        }
        if (it + 2 < 8) Q_ISSUE((it + 2) % 3, (it + 2) * 64);
    }

    // epilogue: q scale (hi) / k LN+split / v LN hi-only
    int mode = blockIdx.x >> 2;          // 0 q, 1 k, 2 v
    const float* lw = (mode == 1) ? ln1w : ln2w;
    const float* lb = (mode == 1) ? ln1b : ln2b;
    __half* dh = (mode == 0) ? g_q_hi : (mode == 1) ? g_k_hi : g_v_hi;
    int colbase = blockIdx.x * 128 - mode * 512 + warpN;   // 0..511 in buffer
#pragma unroll
    for (int mt = 0; mt < 2; mt++) {
#pragma unroll
        for (int hf = 0; hf < 2; hf++) {
            size_t m = (size_t)blockIdx.y * 128 + warpM + mt * 16 + g + hf * 8;
            float v[16];
#pragma unroll
            for (int nt = 0; nt < 8; nt++) {
                v[nt * 2]     = acc[mt][nt][hf * 2];
                v[nt * 2 + 1] = acc[mt][nt][hf * 2 + 1];
            }
            size_t base = m * DIM + colbase + c2 * 2;
            if (mode == 0) {
                int n = (int)(m & (N_TOK - 1));
                float sc = 1.0f / (float)g_sizes[batch[n]];
#pragma unroll
                for (int nt = 0; nt < 8; nt++) {
                    ushort2 uh = make_ushort2(
                        __half_as_ushort(__float2half_rn(v[nt * 2] * sc)),
                        __half_as_ushort(__float2half_rn(v[nt * 2 + 1] * sc)));
                    *(ushort2*)((unsigned short*)dh + base + nt * 8) = uh;
                }
            } else {
                float s = 0.f, s2 = 0.f;
#pragma unroll
                for (int k = 0; k < 16; k++) { s += v[k]; s2 += v[k] * v[k]; }
                s  += __shfl_xor_sync(0xffffffffu, s, 1);
                s  += __shfl_xor_sync(0xffffffffu, s, 2);
                s2 += __shfl_xor_sync(0xffffffffu, s2, 1);
                s2 += __shfl_xor_sync(0xffffffffu, s2, 2);
                float mu = s * (1.0f / 64.0f);
                float var = s2 * (1.0f / 64.0f) - mu * mu;
                float rs = rsqrtf(var + 1e-6f);
#pragma unroll
                for (int nt = 0; nt < 8; nt++) {
                    int cl = ((warpN + nt * 8 + c2 * 2) & 63); // head-local
                    float f0 = (v[nt * 2]     - mu) * rs * lw[cl]     + lb[cl];
                    float f1 = (v[nt * 2 + 1] - mu) * rs * lw[cl + 1] + lb[cl + 1];
                    if (mode == 1) {
                        ushort2 uh, ul;
                        split2(f0, f1, uh, ul);
                        *(ushort2*)((unsigned short*)dh + base + nt * 8) = uh;
                        *(ushort2*)((unsigned short*)g_k_lo + base + nt * 8) = ul;
                    } else {
                        ushort2 uh = make_ushort2(
                            __half_as_ushort(__float2half_rn(f0)),
                            __half_as_ushort(__float2half_rn(f1)));
                        *(ushort2*)((unsigned short*)dh + base + nt * 8) = uh;
                    }
                }
            }
        }
    }
#undef QST
#undef Q_ISSUE
}

// ---------------- GEMM2: out = attn_hi @ w_out^T + bias (1-term, 3-stage) ---
#define OG_SMEM (3 * 2 * TEN_BYTES)   // 110592 -> 2 CTAs/SM

__global__ __launch_bounds__(256, 2)
void out_gemm_kernel(const __half* __restrict__ Ah, const __half* __restrict__ Bh,
                     float* __restrict__ C, const float* __restrict__ bias) {
    extern __shared__ __align__(16) char smem[];
    uint32_t sb = smem_u32(smem);
    int tid = threadIdx.x, wid = tid >> 5, lane = tid & 31;
    int warpM = (wid & 3) * 32;
    int warpN = (wid >> 2) * 64;
    int g = lane >> 2, c2 = lane & 3;

    uint32_t aoff = (lane & 15) * 144 + (lane >> 4) * 16;
    uint32_t boff = ((lane & 7) + ((lane >> 4) << 3)) * 144 + ((lane >> 3) & 1) * 16;

    const __half* pAh = Ah + (size_t)blockIdx.y * 128 * KDIM;
    const __half* pBh = Bh + (size_t)blockIdx.x * 128 * KDIM;

#define OST(s, t) (sb + ((s) * 2 + (t)) * TEN_BYTES)
#define O_ISSUE(s, k0)                            \
    do {                                          \
        issue_slab(OST(s, 0), pAh, (k0), tid);    \
        issue_slab(OST(s, 1), pBh, (k0), tid);    \
        asm volatile("cp.async.commit_group;");   \
    } while (0)

    O_ISSUE(0, 0);
    O_ISSUE(1, 64);

    float acc[2][8][4];
#pragma unroll
    for (int i = 0; i < 2; i++)
#pragma unroll
        for (int j = 0; j < 8; j++)
#pragma unroll
            for (int k = 0; k < 4; k++) acc[i][j][k] = 0.0f;

    for (int it = 0; it < 8; it++) {
        int s = it % 3;
        if (it < 7) asm volatile("cp.async.wait_group 1;");
        else        asm volatile("cp.async.wait_group 0;");
        __syncthreads();   // single barrier (3-stage ring)
        uint32_t aA0 = OST(s, 0) + warpM * 144 + aoff;
        uint32_t aB0 = OST(s, 1) + warpN * 144 + boff;
#pragma unroll
        for (int kk = 0; kk < 4; kk++) {
            int ko = kk * 32;
            uint32_t ah[2][4], bf[4][4];
            LDMX4(ah[0], aA0 + ko); LDMX4(ah[1], aA0 + 16 * 144 + ko);
#pragma unroll
            for (int p = 0; p < 4; p++) LDMX4(bf[p], aB0 + p * 16 * 144 + ko);
#pragma unroll
            for (int mt = 0; mt < 2; mt++)
#pragma unroll
                for (int nt = 0; nt < 8; nt++)
                    mma16816(acc[mt][nt], ah[mt], &bf[nt >> 1][(nt & 1) * 2]);
        }
        if (it + 2 < 8) O_ISSUE((it + 2) % 3, (it + 2) * 64);
    }

#pragma unroll
    for (int mt = 0; mt < 2; mt++) {
        size_t m0 = (size_t)blockIdx.y * 128 + warpM + mt * 16 + g;
#pragma unroll
        for (int nt = 0; nt < 8; nt++) {
            int nc = blockIdx.x * 128 + warpN + nt * 8 + c2 * 2;
            float b0 = bias[nc], b1 = bias[nc + 1];
            *(float2*)(C + m0 * DIM + nc) =
                make_float2(acc[mt][nt][0] + b0, acc[mt][nt][1] + b1);
            *(float2*)(C + (m0 + 8) * DIM + nc) =
                make_float2(acc[mt][nt][2] + b0, acc[mt][nt][3] + b1);
        }
    }
#undef OST
#undef O_ISSUE
}

// ---------------- ktvT[b,h,g] (tensor, 2-term: vh*(kh+kl)) ------------------
#define KT_SLAB  (64 * 144)
#define KT_STAGE (3 * KT_SLAB)
#define KT_SMEM  (2 * KT_STAGE)      // 55296

__global__ __launch_bounds__(128, 2)
void ktvmma_kernel() {
    int gseg = blockIdx.x & 31;
    int h = (blockIdx.x >> 5) & 7;
    int b = blockIdx.x >> 8;
    int s0 = g_off[gseg], s1 = g_off[gseg + 1];
    int NCH = (s1 - s0 + 63) >> 6;
    if (NCH <= 0) NCH = 1;

    extern __shared__ __align__(16) char smem[];
    uint32_t sb = smem_u32(smem);
    int tid = threadIdx.x, wid = tid >> 5, lane = tid & 31;
    int lg = lane >> 2, c2 = lane & 3;

#define KT_ISSUE(st, c)                                                        \
    do {                                                                       \
        int t0 = s0 + (c) * 64;                                                \
        uint32_t base = sb + (st) * KT_STAGE;                                  \
        char* cbase = smem + (st) * KT_STAGE;                                  \
        _Pragma("unroll")                                                      \
        for (int i = 0; i < 4; i++) {                                          \
            int id = tid + i * 128;                                            \
            int row = id >> 3, ch = id & 7;                                    \
            int tok = t0 + row;                                                \
            uint32_t so = row * 144 + ch * 16;                                 \
            if (tok < s1) {                                                    \
                size_t go = ((size_t)b * N_TOK + tok) * DIM + h * DH + ch * 8; \
                CPA16(base + 0 * KT_SLAB + so, g_k_hi + go);                   \
                CPA16(base + 1 * KT_SLAB + so, g_k_lo + go);                   \
                CPA16(base + 2 * KT_SLAB + so, g_v_hi + go);                   \
            } else {                                                           \
                uint4 z = make_uint4(0, 0, 0, 0);                              \
                *(uint4*)(cbase + 0 * KT_SLAB + so) = z;                       \
                *(uint4*)(cbase + 1 * KT_SLAB + so) = z;                       \
                *(uint4*)(cbase + 2 * KT_SLAB + so) = z;                       \
            }                                                                  \
        }                                                                      \
        asm volatile("cp.async.commit_group;");                                \
    } while (0)

    KT_ISSUE(0, 0);
    if (NCH > 1) KT_ISSUE(1, 1);

    uint32_t aoffT = ((lane & 7) + (lane >> 4) * 8) * 144 + ((lane >> 3) & 1) * 16;
    uint32_t boffT = ((lane & 7) + ((lane >> 3) & 1) * 8) * 144 + (lane >> 4) * 16;

    float acc[8][4];
#pragma unroll
    for (int j = 0; j < 8; j++)
#pragma unroll
        for (int k = 0; k < 4; k++) acc[j][k] = 0.0f;

    for (int c = 0; c < NCH; c++) {
        int st = c & 1;
        if (c + 2 <= NCH) asm volatile("cp.async.wait_group 1;");
        else              asm volatile("cp.async.wait_group 0;");
        __syncthreads();
        uint32_t base = sb + st * KT_STAGE;
        uint32_t aKh = base + 0 * KT_SLAB + boffT;
        uint32_t aKl = base + 1 * KT_SLAB + boffT;
        uint32_t aVh = base + 2 * KT_SLAB + wid * 32 + aoffT;
#pragma unroll
        for (int kk = 0; kk < 4; kk++) {
            int ko = kk * (16 * 144);
            uint32_t vh[4], kh[4][4], kl[4][4];
            LDMX4T(vh, aVh + ko);
#pragma unroll
            for (int nb = 0; nb < 4; nb++) {
                LDMX4T(kh[nb], aKh + nb * 32 + ko);
                LDMX4T(kl[nb], aKl + nb * 32 + ko);
            }
#pragma unroll
            for (int nt = 0; nt < 8; nt++) {
                mma16816(acc[nt], vh, &kh[nt >> 1][(nt & 1) * 2]);
                mma16816(acc[nt], vh, &kl[nt >> 1][(nt & 1) * 2]);
            }
        }
        __syncthreads();
        if (c + 2 < NCH) KT_ISSUE(st, c + 2);
    }

    size_t kb = (size_t)blockIdx.x * (DH * DH);
    int r0 = wid * 16 + lg;
#pragma unroll
    for (int nt = 0; nt < 8; nt++) {
        int cidx = nt * 8 + c2 * 2;
        ushort2 uh, ul;
        split2(acc[nt][0], acc[nt][1], uh, ul);
        *(ushort2*)((unsigned short*)g_ktvT_hi + kb + (size_t)r0 * DH + cidx) = uh;
        *(ushort2*)((unsigned short*)g_ktvT_lo + kb + (size_t)r0 * DH + cidx) = ul;
        split2(acc[nt][2], acc[nt][3], uh, ul);
        *(ushort2*)((unsigned short*)g_ktvT_hi + kb + (size_t)(r0 + 8) * DH + cidx) = uh;
        *(ushort2*)((unsigned short*)g_ktvT_lo + kb + (size_t)(r0 + 8) * DH + cidx) = ul;
    }
#undef KT_ISSUE
}

// ---------------- attn tile = qh @ (Th + Tl) (tensor, 2-term) ---------------
#define AP_QSLAB (128 * 144)
#define AP_TSLAB (64 * 144)
#define AP_SMEM  (AP_QSLAB + 2 * AP_TSLAB)   // 36864

__global__ __launch_bounds__(256, 2)
void applymma_kernel() {
    int h = blockIdx.x, ti = blockIdx.y, b = blockIdx.z;
    int nval = g_tile_nval[ti];
    if (nval == 0) return;
    int gseg = g_tile_g[ti];
    int tok0 = g_tile_tok0[ti];

    extern __shared__ __align__(16) char smem[];
    uint32_t sb = smem_u32(smem);
    uint32_t sQh = sb;
    uint32_t sTh = sb + AP_QSLAB, sTl = sTh + AP_TSLAB;

    int tid = threadIdx.x, wid = tid >> 5, lane = tid & 31;
    int warpM = (wid & 3) * 32;
    int warpN = (wid >> 2) * 32;
    int g = lane >> 2, c2 = lane & 3;

    {
        size_t qrow0 = (size_t)b * N_TOK + tok0;
#pragma unroll
        for (int t = 0; t < 4; t++) {
            int id = tid + t * 256;          // 0..1023
            int row = id >> 3, ch = id & 7;
            size_t go = (qrow0 + row) * DIM + h * DH + ch * 8;
            CPA16(sQh + row * 144 + ch * 16, (const __half*)g_q_hi + go);
        }
        size_t kbase = ((size_t)((b * HEADS + h) * NGRAPH + gseg)) * DH * DH;
#pragma unroll
        for (int t = 0; t < 2; t++) {
            int id = tid + t * 256;          // 0..511
            int row = id >> 3, ch = id & 7;
            size_t ko = kbase + (size_t)row * DH + ch * 8;
            CPA16(sTh + row * 144 + ch * 16, (const __half*)g_ktvT_hi + ko);
            CPA16(sTl + row * 144 + ch * 16, (const __half*)g_ktvT_lo + ko);
        }
        asm volatile("cp.async.commit_group;");
        asm volatile("cp.async.wait_group 0;");
        __syncthreads();
    }

    uint32_t aoff = (lane & 15) * 144 + (lane >> 4) * 16;
    uint32_t boff = ((lane & 7) + ((lane >> 4) << 3)) * 144 + ((lane >> 3) & 1) * 16;

    float acc[2][4][4];
#pragma unroll
    for (int i = 0; i < 2; i++)
#pragma unroll
        for (int j = 0; j < 4; j++)
#pragma unroll
            for (int k = 0; k < 4; k++) acc[i][j][k] = 0.0f;

    uint32_t aQh = sQh + warpM * 144 + aoff;
    uint32_t aTh = sTh + warpN * 144 + boff;
    uint32_t aTl = sTl + warpN * 144 + boff;

#pragma unroll
    for (int kk = 0; kk < 4; kk++) {
        int ko = kk * 32;
        uint32_t qh[2][4], bh[2][4], bl[2][4];
        LDMX4(qh[0], aQh + ko); LDMX4(qh[1], aQh + 16 * 144 + ko);
        LDMX4(bh[0], aTh + ko); LDMX4(bh[1], aTh + 16 * 144 + ko);
        LDMX4(bl[0], aTl + ko); LDMX4(bl[1], aTl + 16 * 144 + ko);
#pragma unroll
        for (int mt = 0; mt < 2; mt++)
#pragma unroll
            for (int nt = 0; nt < 4; nt++) {
                const uint32_t* bph = &bh[nt >> 1][(nt & 1) * 2];
                const uint32_t* bpl = &bl[nt >> 1][(nt & 1) * 2];
                mma16816(acc[mt][nt], qh[mt], bph);
                mma16816(acc[mt][nt], qh[mt], bpl);
            }
    }

    // masked epilogue -> attn hi only
#pragma unroll
    for (int mt = 0; mt < 2; mt++) {
#pragma unroll
        for (int hf = 0; hf < 2; hf++) {
            int r = warpM + mt * 16 + g + hf * 8;
            if (r < nval) {
                size_t base = ((size_t)b * N_TOK + tok0 + r) * DIM + h * DH + warpN + c2 * 2;
#pragma unroll
                for (int nt = 0; nt < 4; nt++) {
                    float f0 = acc[mt][nt][hf * 2], f1 = acc[mt][nt][hf * 2 + 1];
                    ushort2 uh = make_ushort2(
                        __half_as_ushort(__float2half_rn(f0)),
                        __half_as_ushort(__float2half_rn(f1)));
                    *(ushort2*)((unsigned short*)g_attn_hi + base + nt * 8) = uh;
                }
            }
        }
    }
}

// ---------------- launch ----------------------------------------------------
extern "C" void kernel_launch(void* const* d_in, const int* in_sizes, int n_in,
                              void* d_out, int out_size) {
    const float* x     = (const float*)d_in[0];
    const float* w_qkv = (const float*)d_in[1];
    const float* ln1w  = (const float*)d_in[2];
    const float* ln1b  = (const float*)d_in[3];
    const float* ln2w  = (const float*)d_in[4];
    const float* ln2b  = (const float*)d_in[5];
    const float* w_out = (const float*)d_in[6];
    const float* b_out = (const float*)d_in[7];
    const int*   batch = (const int*)d_in[8];
    float* out = (float*)d_out;

    __half *ah_p, *b1h_p, *b2h_p, *ath_p;
    cudaGetSymbolAddress((void**)&ah_p,  g_a_hi);
    cudaGetSymbolAddress((void**)&b1h_p, g_b1_hi);
    cudaGetSymbolAddress((void**)&b2h_p, g_b2_hi);
    cudaGetSymbolAddress((void**)&ath_p, g_attn_hi);

    cudaFuncSetAttribute(qkv_gemm_kernel, cudaFuncAttributeMaxDynamicSharedMemorySize, QK_SMEM);
    cudaFuncSetAttribute(out_gemm_kernel, cudaFuncAttributeMaxDynamicSharedMemorySize, OG_SMEM);
    cudaFuncSetAttribute(ktvmma_kernel,   cudaFuncAttributeMaxDynamicSharedMemorySize, KT_SMEM);
    cudaFuncSetAttribute(applymma_kernel, cudaFuncAttributeMaxDynamicSharedMemorySize, AP_SMEM);

    // 0) segment offsets + tile tables
    hist_kernel<<<1, 256>>>(batch);

    // 1) conversions
    conv_round_kernel<<<4096, 256>>>(x, ah_p, (long)M_ROWS * KDIM / 4);
    conv_w_kernel<<<1024, 256>>>(w_qkv, w_out);

    // 2) qkv GEMM (1-term fp16, 3-stage) + fused epilogue
    qkv_gemm_kernel<<<dim3(QKV3 / 128, M_ROWS / 128), 256, QK_SMEM>>>(
        ah_p, b1h_p, batch, ln1w, ln1b, ln2w, ln2b);

    // 3) ktvT per (b,h,g) (tensor, 2-term vh*(kh+kl))
    ktvmma_kernel<<<B_SZ * HEADS * NGRAPH, 128, KT_SMEM>>>();

    // 4) attn = qh @ (Th+Tl) (tensor, 2-term, masked ragged tiles)
    applymma_kernel<<<dim3(HEADS, TILEMAX, B_SZ), 256, AP_SMEM>>>();

    // 5) out = attn_hi @ w_outT + bias (1-term, 3-stage)
    out_gemm_kernel<<<dim3(DIM / 128, M_ROWS / 128), 256, OG_SMEM>>>(
        ath_p, b2h_p, out, b_out);
}

// round 15
// speedup vs baseline: 1.2988x; 1.0754x over previous
#include <cuda_runtime.h>
#include <cuda_fp16.h>
#include <cstdint>

// ---------------- problem constants (fixed by setup_inputs) ----------------
#define B_SZ   2
#define N_TOK  32768
#define DIM    512
#define HEADS  8
#define DH     64
#define NGRAPH 32
#define QKV3   1536
#define M_ROWS (B_SZ * N_TOK)          // 65536
#define KDIM   512
#define TILEMAX 288                    // max token-tiles per batch

// ---------------- device scratch (static; no allocations allowed) ----------
__device__ __half g_a_hi[(size_t)M_ROWS * KDIM];
__device__ __half g_b1_hi[QKV3 * KDIM];
__device__ __half g_b2_hi[DIM * KDIM];
__device__ __half g_q_hi[((size_t)M_ROWS + 128) * DIM];   // +128 slack rows
__device__ __half g_k_hi[(size_t)M_ROWS * DIM];
__device__ __half g_v_hi[(size_t)M_ROWS * DIM];
__device__ __half g_attn_hi[(size_t)M_ROWS * DIM];
__device__ __half g_ktvT_hi[B_SZ * HEADS * NGRAPH * DH * DH];
__device__ int    g_sizes[NGRAPH];
__device__ int    g_off [NGRAPH + 1];
__device__ int    g_tile_g[TILEMAX];
__device__ int    g_tile_tok0[TILEMAX];
__device__ int    g_tile_nval[TILEMAX];

// ---------------- helpers ---------------------------------------------------
__device__ __forceinline__ uint32_t smem_u32(const void* p) {
    uint32_t a;
    asm("{ .reg .u64 t; cvta.to.shared.u64 t, %1; cvt.u32.u64 %0, t; }"
        : "=r"(a) : "l"(p));
    return a;
}
__device__ __forceinline__ void mma16816(float* d, const uint32_t* a, const uint32_t* b) {
    asm volatile(
        "mma.sync.aligned.m16n8k16.row.col.f32.f16.f16.f32 "
        "{%0,%1,%2,%3}, {%4,%5,%6,%7}, {%8,%9}, {%0,%1,%2,%3};"
        : "+f"(d[0]), "+f"(d[1]), "+f"(d[2]), "+f"(d[3])
        : "r"(a[0]), "r"(a[1]), "r"(a[2]), "r"(a[3]), "r"(b[0]), "r"(b[1]));
}
#define LDMX4(r, addr) \
    asm volatile("ldmatrix.sync.aligned.m8n8.x4.shared.b16 {%0,%1,%2,%3}, [%4];" \
                 : "=r"((r)[0]), "=r"((r)[1]), "=r"((r)[2]), "=r"((r)[3]) : "r"(addr))
#define LDMX4T(r, addr) \
    asm volatile("ldmatrix.sync.aligned.m8n8.x4.trans.shared.b16 {%0,%1,%2,%3}, [%4];" \
                 : "=r"((r)[0]), "=r"((r)[1]), "=r"((r)[2]), "=r"((r)[3]) : "r"(addr))
#define CPA16(s, gp) \
    asm volatile("cp.async.cg.shared.global [%0], [%1], 16;" :: "r"(s), "l"(gp))

// ---------------- hist + tile tables ----------------------------------------
__global__ void hist_kernel(const int* __restrict__ batch) {
    __shared__ int cnt[NGRAPH];
    int tid = threadIdx.x;
    if (tid < NGRAPH) cnt[tid] = 0;
    __syncthreads();
    for (int i = tid; i < N_TOK; i += 256) atomicAdd(&cnt[batch[i]], 1);
    __syncthreads();
    if (tid == 0) {
        int off = 0;
        for (int g = 0; g < NGRAPH; g++) {
            g_off[g] = off; g_sizes[g] = cnt[g]; off += cnt[g];
        }
        g_off[NGRAPH] = off;
        int t = 0;
        for (int g = 0; g < NGRAPH; g++) {
            int S = g_sizes[g];
            for (int i = 0; i < S; i += 128) {
                g_tile_g[t] = g;
                g_tile_tok0[t] = g_off[g] + i;
                g_tile_nval[t] = (S - i < 128) ? (S - i) : 128;
                t++;
            }
        }
        for (; t < TILEMAX; t++) g_tile_nval[t] = 0;
    }
}

__device__ __forceinline__ ushort4 round4(float4 v) {
    ushort4 r;
    r.x = __half_as_ushort(__float2half_rn(v.x));
    r.y = __half_as_ushort(__float2half_rn(v.y));
    r.z = __half_as_ushort(__float2half_rn(v.z));
    r.w = __half_as_ushort(__float2half_rn(v.w));
    return r;
}

// fp32 -> fp16 round, x4
__global__ void conv_round_kernel(const float* __restrict__ src,
                                  __half* __restrict__ dst, long n4) {
    long i = (long)blockIdx.x * blockDim.x + threadIdx.x;
    long stride = (long)gridDim.x * blockDim.x;
    for (; i < n4; i += stride)
        ((ushort4*)dst)[i] = round4(((const float4*)src)[i]);
}

// weights: fp16 rounding, one launch
__global__ void conv_w_kernel(const float* __restrict__ w1,
                              const float* __restrict__ w2) {
    const long n1 = (long)QKV3 * KDIM / 4;
    const long n2 = (long)DIM * KDIM / 4;
    long i = (long)blockIdx.x * blockDim.x + threadIdx.x;
    long stride = (long)gridDim.x * blockDim.x;
    for (; i < n1 + n2; i += stride) {
        if (i < n1) ((ushort4*)g_b1_hi)[i]      = round4(((const float4*)w1)[i]);
        else        ((ushort4*)g_b2_hi)[i - n1] = round4(((const float4*)w2)[i - n1]);
    }
}

#define TEN_BYTES (128 * 144)

__device__ __forceinline__ void issue_slab(uint32_t sdst, const __half* g,
                                           int k0, int tid) {
#pragma unroll
    for (int t = 0; t < 4; t++) {
        int id  = tid + t * 256;
        int row = id >> 3, col = id & 7;
        CPA16(sdst + row * 144 + col * 16, g + (size_t)row * KDIM + k0 + col * 8);
    }
}

// ---------------- GEMM1: qkv = x16 @ w16^T (1-term fp16, 3-stage ring) ------
// epilogue: q scale->hi, k LN(ln1)->hi, v LN(ln2)->hi  (all single fp16)
#define QK_SMEM (3 * 2 * TEN_BYTES)   // 110592 -> 2 CTAs/SM

__global__ __launch_bounds__(256, 2)
void qkv_gemm_kernel(const __half* __restrict__ Ah, const __half* __restrict__ Bh,
                     const int* __restrict__ batch,
                     const float* __restrict__ ln1w, const float* __restrict__ ln1b,
                     const float* __restrict__ ln2w, const float* __restrict__ ln2b) {
    extern __shared__ __align__(16) char smem[];
    uint32_t sb = smem_u32(smem);
    int tid = threadIdx.x, wid = tid >> 5, lane = tid & 31;
    int warpM = (wid & 3) * 32;
    int warpN = (wid >> 2) * 64;
    int g = lane >> 2, c2 = lane & 3;

    uint32_t aoff = (lane & 15) * 144 + (lane >> 4) * 16;
    uint32_t boff = ((lane & 7) + ((lane >> 4) << 3)) * 144 + ((lane >> 3) & 1) * 16;

    const __half* pAh = Ah + (size_t)blockIdx.y * 128 * KDIM;
    const __half* pBh = Bh + (size_t)blockIdx.x * 128 * KDIM;

#define QST(s, t) (sb + ((s) * 2 + (t)) * TEN_BYTES)
#define Q_ISSUE(s, k0)                            \
    do {                                          \
        issue_slab(QST(s, 0), pAh, (k0), tid);    \
        issue_slab(QST(s, 1), pBh, (k0), tid);    \
        asm volatile("cp.async.commit_group;");   \
    } while (0)

    Q_ISSUE(0, 0);
    Q_ISSUE(1, 64);

    float acc[2][8][4];
#pragma unroll
    for (int i = 0; i < 2; i++)
#pragma unroll
        for (int j = 0; j < 8; j++)
#pragma unroll
            for (int k = 0; k < 4; k++) acc[i][j][k] = 0.0f;

    for (int it = 0; it < 8; it++) {
        int s = it % 3;
        if (it < 7) asm volatile("cp.async.wait_group 1;");
        else        asm volatile("cp.async.wait_group 0;");
        __syncthreads();   // single barrier: frees stage (it+2)%3 too
        uint32_t aA0 = QST(s, 0) + warpM * 144 + aoff;
        uint32_t aB0 = QST(s, 1) + warpN * 144 + boff;
#pragma unroll
        for (int kk = 0; kk < 4; kk++) {
            int ko = kk * 32;
            uint32_t ah[2][4], bf[4][4];
            LDMX4(ah[0], aA0 + ko); LDMX4(ah[1], aA0 + 16 * 144 + ko);
#pragma unroll
            for (int p = 0; p < 4; p++) LDMX4(bf[p], aB0 + p * 16 * 144 + ko);
#pragma unroll
            for (int mt = 0; mt < 2; mt++)
#pragma unroll
                for (int nt = 0; nt < 8; nt++)
                    mma16816(acc[mt][nt], ah[mt], &bf[nt >> 1][(nt & 1) * 2]);
        }
        if (it + 2 < 8) Q_ISSUE((it + 2) % 3, (it + 2) * 64);
    }

    // epilogue: q scale / k LN / v LN, all -> single fp16
    int mode = blockIdx.x >> 2;          // 0 q, 1 k, 2 v
    const float* lw = (mode == 1) ? ln1w : ln2w;
    const float* lb = (mode == 1) ? ln1b : ln2b;
    __half* dh = (mode == 0) ? g_q_hi : (mode == 1) ? g_k_hi : g_v_hi;
    int colbase = blockIdx.x * 128 - mode * 512 + warpN;   // 0..511 in buffer
#pragma unroll
    for (int mt = 0; mt < 2; mt++) {
#pragma unroll
        for (int hf = 0; hf < 2; hf++) {
            size_t m = (size_t)blockIdx.y * 128 + warpM + mt * 16 + g + hf * 8;
            float v[16];
#pragma unroll
            for (int nt = 0; nt < 8; nt++) {
                v[nt * 2]     = acc[mt][nt][hf * 2];
                v[nt * 2 + 1] = acc[mt][nt][hf * 2 + 1];
            }
            size_t base = m * DIM + colbase + c2 * 2;
            if (mode == 0) {
                int n = (int)(m & (N_TOK - 1));
                float sc = 1.0f / (float)g_sizes[batch[n]];
#pragma unroll
                for (int k = 0; k < 16; k++) v[k] *= sc;
            } else {
                float s = 0.f, s2 = 0.f;
#pragma unroll
                for (int k = 0; k < 16; k++) { s += v[k]; s2 += v[k] * v[k]; }
                s  += __shfl_xor_sync(0xffffffffu, s, 1);
                s  += __shfl_xor_sync(0xffffffffu, s, 2);
                s2 += __shfl_xor_sync(0xffffffffu, s2, 1);
                s2 += __shfl_xor_sync(0xffffffffu, s2, 2);
                float mu = s * (1.0f / 64.0f);
                float var = s2 * (1.0f / 64.0f) - mu * mu;
                float rs = rsqrtf(var + 1e-6f);
#pragma unroll
                for (int nt = 0; nt < 8; nt++) {
                    int cl = ((warpN + nt * 8 + c2 * 2) & 63); // head-local
                    v[nt * 2]     = (v[nt * 2]     - mu) * rs * lw[cl]     + lb[cl];
                    v[nt * 2 + 1] = (v[nt * 2 + 1] - mu) * rs * lw[cl + 1] + lb[cl + 1];
                }
            }
#pragma unroll
            for (int nt = 0; nt < 8; nt++) {
                ushort2 uh = make_ushort2(
                    __half_as_ushort(__float2half_rn(v[nt * 2])),
                    __half_as_ushort(__float2half_rn(v[nt * 2 + 1])));
                *(ushort2*)((unsigned short*)dh + base + nt * 8) = uh;
            }
        }
    }
#undef QST
#undef Q_ISSUE
}

// ---------------- GEMM2: out = attn_hi @ w_out^T + bias (1-term, 3-stage) ---
#define OG_SMEM (3 * 2 * TEN_BYTES)   // 110592 -> 2 CTAs/SM

__global__ __launch_bounds__(256, 2)
void out_gemm_kernel(const __half* __restrict__ Ah, const __half* __restrict__ Bh,
                     float* __restrict__ C, const float* __restrict__ bias) {
    extern __shared__ __align__(16) char smem[];
    uint32_t sb = smem_u32(smem);
    int tid = threadIdx.x, wid = tid >> 5, lane = tid & 31;
    int warpM = (wid & 3) * 32;
    int warpN = (wid >> 2) * 64;
    int g = lane >> 2, c2 = lane & 3;

    uint32_t aoff = (lane & 15) * 144 + (lane >> 4) * 16;
    uint32_t boff = ((lane & 7) + ((lane >> 4) << 3)) * 144 + ((lane >> 3) & 1) * 16;

    const __half* pAh = Ah + (size_t)blockIdx.y * 128 * KDIM;
    const __half* pBh = Bh + (size_t)blockIdx.x * 128 * KDIM;

#define OST(s, t) (sb + ((s) * 2 + (t)) * TEN_BYTES)
#define O_ISSUE(s, k0)                            \
    do {                                          \
        issue_slab(OST(s, 0), pAh, (k0), tid);    \
        issue_slab(OST(s, 1), pBh, (k0), tid);    \
        asm volatile("cp.async.commit_group;");   \
    } while (0)

    O_ISSUE(0, 0);
    O_ISSUE(1, 64);

    float acc[2][8][4];
#pragma unroll
    for (int i = 0; i < 2; i++)
#pragma unroll
        for (int j = 0; j < 8; j++)
#pragma unroll
            for (int k = 0; k < 4; k++) acc[i][j][k] = 0.0f;

    for (int it = 0; it < 8; it++) {
        int s = it % 3;
        if (it < 7) asm volatile("cp.async.wait_group 1;");
        else        asm volatile("cp.async.wait_group 0;");
        __syncthreads();   // single barrier (3-stage ring)
        uint32_t aA0 = OST(s, 0) + warpM * 144 + aoff;
        uint32_t aB0 = OST(s, 1) + warpN * 144 + boff;
#pragma unroll
        for (int kk = 0; kk < 4; kk++) {
            int ko = kk * 32;
            uint32_t ah[2][4], bf[4][4];
            LDMX4(ah[0], aA0 + ko); LDMX4(ah[1], aA0 + 16 * 144 + ko);
#pragma unroll
            for (int p = 0; p < 4; p++) LDMX4(bf[p], aB0 + p * 16 * 144 + ko);
#pragma unroll
            for (int mt = 0; mt < 2; mt++)
#pragma unroll
                for (int nt = 0; nt < 8; nt++)
                    mma16816(acc[mt][nt], ah[mt], &bf[nt >> 1][(nt & 1) * 2]);
        }
        if (it + 2 < 8) O_ISSUE((it + 2) % 3, (it + 2) * 64);
    }

#pragma unroll
    for (int mt = 0; mt < 2; mt++) {
        size_t m0 = (size_t)blockIdx.y * 128 + warpM + mt * 16 + g;
#pragma unroll
        for (int nt = 0; nt < 8; nt++) {
            int nc = blockIdx.x * 128 + warpN + nt * 8 + c2 * 2;
            float b0 = bias[nc], b1 = bias[nc + 1];
            *(float2*)(C + m0 * DIM + nc) =
                make_float2(acc[mt][nt][0] + b0, acc[mt][nt][1] + b1);
            *(float2*)(C + (m0 + 8) * DIM + nc) =
                make_float2(acc[mt][nt][2] + b0, acc[mt][nt][3] + b1);
        }
    }
#undef OST
#undef O_ISSUE
}

// ---------------- ktvT[b,h,g] (tensor, 1-term: vh*kh) -----------------------
#define KT_SLAB  (64 * 144)
#define KT_STAGE (2 * KT_SLAB)
#define KT_SMEM  (2 * KT_STAGE)      // 36864

__global__ __launch_bounds__(128, 2)
void ktvmma_kernel() {
    int gseg = blockIdx.x & 31;
    int h = (blockIdx.x >> 5) & 7;
    int b = blockIdx.x >> 8;
    int s0 = g_off[gseg], s1 = g_off[gseg + 1];
    int NCH = (s1 - s0 + 63) >> 6;
    if (NCH <= 0) NCH = 1;

    extern __shared__ __align__(16) char smem[];
    uint32_t sb = smem_u32(smem);
    int tid = threadIdx.x, wid = tid >> 5, lane = tid & 31;
    int lg = lane >> 2, c2 = lane & 3;

#define KT_ISSUE(st, c)                                                        \
    do {                                                                       \
        int t0 = s0 + (c) * 64;                                                \
        uint32_t base = sb + (st) * KT_STAGE;                                  \
        char* cbase = smem + (st) * KT_STAGE;                                  \
        _Pragma("unroll")                                                      \
        for (int i = 0; i < 4; i++) {                                          \
            int id = tid + i * 128;                                            \
            int row = id >> 3, ch = id & 7;                                    \
            int tok = t0 + row;                                                \
            uint32_t so = row * 144 + ch * 16;                                 \
            if (tok < s1) {                                                    \
                size_t go = ((size_t)b * N_TOK + tok) * DIM + h * DH + ch * 8; \
                CPA16(base + 0 * KT_SLAB + so, g_k_hi + go);                   \
                CPA16(base + 1 * KT_SLAB + so, g_v_hi + go);                   \
            } else {                                                           \
                uint4 z = make_uint4(0, 0, 0, 0);                              \
                *(uint4*)(cbase + 0 * KT_SLAB + so) = z;                       \
                *(uint4*)(cbase + 1 * KT_SLAB + so) = z;                       \
            }                                                                  \
        }                                                                      \
        asm volatile("cp.async.commit_group;");                                \
    } while (0)

    KT_ISSUE(0, 0);
    if (NCH > 1) KT_ISSUE(1, 1);

    uint32_t aoffT = ((lane & 7) + (lane >> 4) * 8) * 144 + ((lane >> 3) & 1) * 16;
    uint32_t boffT = ((lane & 7) + ((lane >> 3) & 1) * 8) * 144 + (lane >> 4) * 16;

    float acc[8][4];
#pragma unroll
    for (int j = 0; j < 8; j++)
#pragma unroll
        for (int k = 0; k < 4; k++) acc[j][k] = 0.0f;

    for (int c = 0; c < NCH; c++) {
        int st = c & 1;
        if (c + 2 <= NCH) asm volatile("cp.async.wait_group 1;");
        else              asm volatile("cp.async.wait_group 0;");
        __syncthreads();
        uint32_t base = sb + st * KT_STAGE;
        uint32_t aKh = base + 0 * KT_SLAB + boffT;
        uint32_t aVh = base + 1 * KT_SLAB + wid * 32 + aoffT;
#pragma unroll
        for (int kk = 0; kk < 4; kk++) {
            int ko = kk * (16 * 144);
            uint32_t vh[4], kh[4][4];
            LDMX4T(vh, aVh + ko);
#pragma unroll
            for (int nb = 0; nb < 4; nb++)
                LDMX4T(kh[nb], aKh + nb * 32 + ko);
#pragma unroll
            for (int nt = 0; nt < 8; nt++)
                mma16816(acc[nt], vh, &kh[nt >> 1][(nt & 1) * 2]);
        }
        __syncthreads();
        if (c + 2 < NCH) KT_ISSUE(st, c + 2);
    }

    size_t kb = (size_t)blockIdx.x * (DH * DH);
    int r0 = wid * 16 + lg;
#pragma unroll
    for (int nt = 0; nt < 8; nt++) {
        int cidx = nt * 8 + c2 * 2;
        ushort2 u0 = make_ushort2(
            __half_as_ushort(__float2half_rn(acc[nt][0])),
            __half_as_ushort(__float2half_rn(acc[nt][1])));
        ushort2 u1 = make_ushort2(
            __half_as_ushort(__float2half_rn(acc[nt][2])),
            __half_as_ushort(__float2half_rn(acc[nt][3])));
        *(ushort2*)((unsigned short*)g_ktvT_hi + kb + (size_t)r0 * DH + cidx) = u0;
        *(ushort2*)((unsigned short*)g_ktvT_hi + kb + (size_t)(r0 + 8) * DH + cidx) = u1;
    }
#undef KT_ISSUE
}

// ---------------- attn tile = qh @ Th (tensor, 1-term) ----------------------
#define AP_QSLAB (128 * 144)
#define AP_TSLAB (64 * 144)
#define AP_SMEM  (AP_QSLAB + AP_TSLAB)   // 27648

__global__ __launch_bounds__(256, 2)
void applymma_kernel() {
    int h = blockIdx.x, ti = blockIdx.y, b = blockIdx.z;
    int nval = g_tile_nval[ti];
    if (nval == 0) return;
    int gseg = g_tile_g[ti];
    int tok0 = g_tile_tok0[ti];

    extern __shared__ __align__(16) char smem[];
    uint32_t sb = smem_u32(smem);
    uint32_t sQh = sb;
    uint32_t sTh = sb + AP_QSLAB;

    int tid = threadIdx.x, wid = tid >> 5, lane = tid & 31;
    int warpM = (wid & 3) * 32;
    int warpN = (wid >> 2) * 32;
    int g = lane >> 2, c2 = lane & 3;

    {
        size_t qrow0 = (size_t)b * N_TOK + tok0;
#pragma unroll
        for (int t = 0; t < 4; t++) {
            int id = tid + t * 256;          // 0..1023
            int row = id >> 3, ch = id & 7;
            size_t go = (qrow0 + row) * DIM + h * DH + ch * 8;
            CPA16(sQh + row * 144 + ch * 16, (const __half*)g_q_hi + go);
        }
        size_t kbase = ((size_t)((b * HEADS + h) * NGRAPH + gseg)) * DH * DH;
#pragma unroll
        for (int t = 0; t < 2; t++) {
            int id = tid + t * 256;          // 0..511
            int row = id >> 3, ch = id & 7;
            size_t ko = kbase + (size_t)row * DH + ch * 8;
            CPA16(sTh + row * 144 + ch * 16, (const __half*)g_ktvT_hi + ko);
        }
        asm volatile("cp.async.commit_group;");
        asm volatile("cp.async.wait_group 0;");
        __syncthreads();
    }

    uint32_t aoff = (lane & 15) * 144 + (lane >> 4) * 16;
    uint32_t boff = ((lane & 7) + ((lane >> 4) << 3)) * 144 + ((lane >> 3) & 1) * 16;

    float acc[2][4][4];
#pragma unroll
    for (int i = 0; i < 2; i++)
#pragma unroll
        for (int j = 0; j < 4; j++)
#pragma unroll
            for (int k = 0; k < 4; k++) acc[i][j][k] = 0.0f;

    uint32_t aQh = sQh + warpM * 144 + aoff;
    uint32_t aTh = sTh + warpN * 144 + boff;

#pragma unroll
    for (int kk = 0; kk < 4; kk++) {
        int ko = kk * 32;
        uint32_t qh[2][4], bh[2][4];
        LDMX4(qh[0], aQh + ko); LDMX4(qh[1], aQh + 16 * 144 + ko);
        LDMX4(bh[0], aTh + ko); LDMX4(bh[1], aTh + 16 * 144 + ko);
#pragma unroll
        for (int mt = 0; mt < 2; mt++)
#pragma unroll
            for (int nt = 0; nt < 4; nt++)
                mma16816(acc[mt][nt], qh[mt], &bh[nt >> 1][(nt & 1) * 2]);
    }

    // masked epilogue -> attn hi
#pragma unroll
    for (int mt = 0; mt < 2; mt++) {
#pragma unroll
        for (int hf = 0; hf < 2; hf++) {
            int r = warpM + mt * 16 + g + hf * 8;
            if (r < nval) {
                size_t base = ((size_t)b * N_TOK + tok0 + r) * DIM + h * DH + warpN + c2 * 2;
#pragma unroll
                for (int nt = 0; nt < 4; nt++) {
                    float f0 = acc[mt][nt][hf * 2], f1 = acc[mt][nt][hf * 2 + 1];
                    ushort2 uh = make_ushort2(
                        __half_as_ushort(__float2half_rn(f0)),
                        __half_as_ushort(__float2half_rn(f1)));
                    *(ushort2*)((unsigned short*)g_attn_hi + base + nt * 8) = uh;
                }
            }
        }
    }
}

// ---------------- launch ----------------------------------------------------
extern "C" void kernel_launch(void* const* d_in, const int* in_sizes, int n_in,
                              void* d_out, int out_size) {
    const float* x     = (const float*)d_in[0];
    const float* w_qkv = (const float*)d_in[1];
    const float* ln1w  = (const float*)d_in[2];
    const float* ln1b  = (const float*)d_in[3];
    const float* ln2w  = (const float*)d_in[4];
    const float* ln2b  = (const float*)d_in[5];
    const float* w_out = (const float*)d_in[6];
    const float* b_out = (const float*)d_in[7];
    const int*   batch = (const int*)d_in[8];
    float* out = (float*)d_out;

    __half *ah_p, *b1h_p, *b2h_p, *ath_p;
    cudaGetSymbolAddress((void**)&ah_p,  g_a_hi);
    cudaGetSymbolAddress((void**)&b1h_p, g_b1_hi);
    cudaGetSymbolAddress((void**)&b2h_p, g_b2_hi);
    cudaGetSymbolAddress((void**)&ath_p, g_attn_hi);

    cudaFuncSetAttribute(qkv_gemm_kernel, cudaFuncAttributeMaxDynamicSharedMemorySize, QK_SMEM);
    cudaFuncSetAttribute(out_gemm_kernel, cudaFuncAttributeMaxDynamicSharedMemorySize, OG_SMEM);
    cudaFuncSetAttribute(ktvmma_kernel,   cudaFuncAttributeMaxDynamicSharedMemorySize, KT_SMEM);
    cudaFuncSetAttribute(applymma_kernel, cudaFuncAttributeMaxDynamicSharedMemorySize, AP_SMEM);

    // 0) segment offsets + tile tables
    hist_kernel<<<1, 256>>>(batch);

    // 1) conversions
    conv_round_kernel<<<4096, 256>>>(x, ah_p, (long)M_ROWS * KDIM / 4);
    conv_w_kernel<<<1024, 256>>>(w_qkv, w_out);

    // 2) qkv GEMM (1-term fp16, 3-stage) + fused epilogue (all hi-only)
    qkv_gemm_kernel<<<dim3(QKV3 / 128, M_ROWS / 128), 256, QK_SMEM>>>(
        ah_p, b1h_p, batch, ln1w, ln1b, ln2w, ln2b);

    // 3) ktvT per (b,h,g) (tensor, 1-term vh*kh)
    ktvmma_kernel<<<B_SZ * HEADS * NGRAPH, 128, KT_SMEM>>>();

    // 4) attn = qh @ Th (tensor, 1-term, masked ragged tiles)
    applymma_kernel<<<dim3(HEADS, TILEMAX, B_SZ), 256, AP_SMEM>>>();

    // 5) out = attn_hi @ w_outT + bias (1-term, 3-stage)
    out_gemm_kernel<<<dim3(DIM / 128, M_ROWS / 128), 256, OG_SMEM>>>(
        ath_p, b2h_p, out, b_out);
}

// round 16
// speedup vs baseline: 1.3093x; 1.0081x over previous
#include <cuda_runtime.h>
#include <cuda_fp16.h>
#include <cstdint>

// ---------------- problem constants (fixed by setup_inputs) ----------------
#define B_SZ   2
#define N_TOK  32768
#define DIM    512
#define HEADS  8
#define DH     64
#define NGRAPH 32
#define QKV3   1536
#define M_ROWS (B_SZ * N_TOK)          // 65536
#define KDIM   512
#define TILEMAX 288                    // max token-tiles per batch

// ---------------- device scratch (static; no allocations allowed) ----------
__device__ __half g_a_hi[(size_t)M_ROWS * KDIM];
__device__ __half g_b1_hi[QKV3 * KDIM];
__device__ __half g_b2_hi[DIM * KDIM];
__device__ __half g_q_hi[((size_t)M_ROWS + 128) * DIM];   // +128 slack rows
__device__ __half g_k_hi[(size_t)M_ROWS * DIM];
__device__ __half g_v_hi[(size_t)M_ROWS * DIM];
__device__ __half g_attn_hi[(size_t)M_ROWS * DIM];
__device__ __half g_ktvT_hi[B_SZ * HEADS * NGRAPH * DH * DH];
__device__ int    g_sizes[NGRAPH];
__device__ int    g_off [NGRAPH + 1];
__device__ int    g_tile_g[TILEMAX];
__device__ int    g_tile_tok0[TILEMAX];
__device__ int    g_tile_nval[TILEMAX];

// ---------------- helpers ---------------------------------------------------
__device__ __forceinline__ uint32_t smem_u32(const void* p) {
    uint32_t a;
    asm("{ .reg .u64 t; cvta.to.shared.u64 t, %1; cvt.u32.u64 %0, t; }"
        : "=r"(a) : "l"(p));
    return a;
}
__device__ __forceinline__ void mma16816(float* d, const uint32_t* a, const uint32_t* b) {
    asm volatile(
        "mma.sync.aligned.m16n8k16.row.col.f32.f16.f16.f32 "
        "{%0,%1,%2,%3}, {%4,%5,%6,%7}, {%8,%9}, {%0,%1,%2,%3};"
        : "+f"(d[0]), "+f"(d[1]), "+f"(d[2]), "+f"(d[3])
        : "r"(a[0]), "r"(a[1]), "r"(a[2]), "r"(a[3]), "r"(b[0]), "r"(b[1]));
}
#define LDMX4(r, addr) \
    asm volatile("ldmatrix.sync.aligned.m8n8.x4.shared.b16 {%0,%1,%2,%3}, [%4];" \
                 : "=r"((r)[0]), "=r"((r)[1]), "=r"((r)[2]), "=r"((r)[3]) : "r"(addr))
#define LDMX4T(r, addr) \
    asm volatile("ldmatrix.sync.aligned.m8n8.x4.trans.shared.b16 {%0,%1,%2,%3}, [%4];" \
                 : "=r"((r)[0]), "=r"((r)[1]), "=r"((r)[2]), "=r"((r)[3]) : "r"(addr))
#define CPA16(s, gp) \
    asm volatile("cp.async.cg.shared.global [%0], [%1], 16;" :: "r"(s), "l"(gp))

__device__ __forceinline__ ushort4 round4(float4 v) {
    ushort4 r;
    r.x = __half_as_ushort(__float2half_rn(v.x));
    r.y = __half_as_ushort(__float2half_rn(v.y));
    r.z = __half_as_ushort(__float2half_rn(v.z));
    r.w = __half_as_ushort(__float2half_rn(v.w));
    return r;
}

// ---------------- prep: hist + tile tables + all fp32->fp16 conversions -----
__global__ void prep_kernel(const float* __restrict__ x,
                            const float* __restrict__ w1,
                            const float* __restrict__ w2,
                            const int* __restrict__ batch) {
    if (blockIdx.x == gridDim.x - 1) {
        // histogram + offsets + tile tables (one block)
        __shared__ int cnt[NGRAPH];
        int tid = threadIdx.x;
        if (tid < NGRAPH) cnt[tid] = 0;
        __syncthreads();
        for (int i = tid; i < N_TOK; i += 256) atomicAdd(&cnt[batch[i]], 1);
        __syncthreads();
        if (tid == 0) {
            int off = 0;
            for (int g = 0; g < NGRAPH; g++) {
                g_off[g] = off; g_sizes[g] = cnt[g]; off += cnt[g];
            }
            g_off[NGRAPH] = off;
            int t = 0;
            for (int g = 0; g < NGRAPH; g++) {
                int S = g_sizes[g];
                for (int i = 0; i < S; i += 128) {
                    g_tile_g[t] = g;
                    g_tile_tok0[t] = g_off[g] + i;
                    g_tile_nval[t] = (S - i < 128) ? (S - i) : 128;
                    t++;
                }
            }
            for (; t < TILEMAX; t++) g_tile_nval[t] = 0;
        }
        return;
    }
    // conversions: concatenated grid-stride range
    const long nx = (long)M_ROWS * KDIM / 4;
    const long n1 = (long)QKV3 * KDIM / 4;
    const long n2 = (long)DIM * KDIM / 4;
    long i = (long)blockIdx.x * blockDim.x + threadIdx.x;
    long stride = (long)(gridDim.x - 1) * blockDim.x;
    for (; i < nx + n1 + n2; i += stride) {
        if (i < nx)
            ((ushort4*)g_a_hi)[i] = round4(((const float4*)x)[i]);
        else if (i < nx + n1)
            ((ushort4*)g_b1_hi)[i - nx] = round4(((const float4*)w1)[i - nx]);
        else
            ((ushort4*)g_b2_hi)[i - nx - n1] = round4(((const float4*)w2)[i - nx - n1]);
    }
}

#define TEN_BYTES (128 * 144)

__device__ __forceinline__ void issue_slab(uint32_t sdst, const __half* g,
                                           int k0, int tid) {
#pragma unroll
    for (int t = 0; t < 4; t++) {
        int id  = tid + t * 256;
        int row = id >> 3, col = id & 7;
        CPA16(sdst + row * 144 + col * 16, g + (size_t)row * KDIM + k0 + col * 8);
    }
}

// ---------------- GEMM1: qkv = x16 @ w16^T (1-term fp16, 3-stage ring) ------
// epilogue: q scale->hi, k LN(ln1)->hi, v LN(ln2)->hi
#define QK_SMEM (3 * 2 * TEN_BYTES)   // 110592 -> 2 CTAs/SM

__global__ __launch_bounds__(256, 2)
void qkv_gemm_kernel(const __half* __restrict__ Ah, const __half* __restrict__ Bh,
                     const int* __restrict__ batch,
                     const float* __restrict__ ln1w, const float* __restrict__ ln1b,
                     const float* __restrict__ ln2w, const float* __restrict__ ln2b) {
    extern __shared__ __align__(16) char smem[];
    uint32_t sb = smem_u32(smem);
    int tid = threadIdx.x, wid = tid >> 5, lane = tid & 31;
    int warpM = (wid & 3) * 32;
    int warpN = (wid >> 2) * 64;
    int g = lane >> 2, c2 = lane & 3;

    uint32_t aoff = (lane & 15) * 144 + (lane >> 4) * 16;
    uint32_t boff = ((lane & 7) + ((lane >> 4) << 3)) * 144 + ((lane >> 3) & 1) * 16;

    const __half* pAh = Ah + (size_t)blockIdx.y * 128 * KDIM;
    const __half* pBh = Bh + (size_t)blockIdx.x * 128 * KDIM;

#define QST(s, t) (sb + ((s) * 2 + (t)) * TEN_BYTES)
#define Q_ISSUE(s, k0)                            \
    do {                                          \
        issue_slab(QST(s, 0), pAh, (k0), tid);    \
        issue_slab(QST(s, 1), pBh, (k0), tid);    \
        asm volatile("cp.async.commit_group;");   \
    } while (0)

    Q_ISSUE(0, 0);
    Q_ISSUE(1, 64);

    float acc[2][8][4];
#pragma unroll
    for (int i = 0; i < 2; i++)
#pragma unroll
        for (int j = 0; j < 8; j++)
#pragma unroll
            for (int k = 0; k < 4; k++) acc[i][j][k] = 0.0f;

    for (int it = 0; it < 8; it++) {
        int s = it % 3;
        if (it < 7) asm volatile("cp.async.wait_group 1;");
        else        asm volatile("cp.async.wait_group 0;");
        __syncthreads();   // single barrier: frees stage (it+2)%3 too
        uint32_t aA0 = QST(s, 0) + warpM * 144 + aoff;
        uint32_t aB0 = QST(s, 1) + warpN * 144 + boff;
#pragma unroll
        for (int kk = 0; kk < 4; kk++) {
            int ko = kk * 32;
            uint32_t ah[2][4], bf[4][4];
            LDMX4(ah[0], aA0 + ko); LDMX4(ah[1], aA0 + 16 * 144 + ko);
#pragma unroll
            for (int p = 0; p < 4; p++) LDMX4(bf[p], aB0 + p * 16 * 144 + ko);
#pragma unroll
            for (int mt = 0; mt < 2; mt++)
#pragma unroll
                for (int nt = 0; nt < 8; nt++)
                    mma16816(acc[mt][nt], ah[mt], &bf[nt >> 1][(nt & 1) * 2]);
        }
        if (it + 2 < 8) Q_ISSUE((it + 2) % 3, (it + 2) * 64);
    }

    // epilogue: q scale / k LN / v LN, all -> single fp16
    int mode = blockIdx.x >> 2;          // 0 q, 1 k, 2 v
    const float* lw = (mode == 1) ? ln1w : ln2w;
    const float* lb = (mode == 1) ? ln1b : ln2b;
    __half* dh = (mode == 0) ? g_q_hi : (mode == 1) ? g_k_hi : g_v_hi;
    int colbase = blockIdx.x * 128 - mode * 512 + warpN;   // 0..511 in buffer
#pragma unroll
    for (int mt = 0; mt < 2; mt++) {
#pragma unroll
        for (int hf = 0; hf < 2; hf++) {
            size_t m = (size_t)blockIdx.y * 128 + warpM + mt * 16 + g + hf * 8;
            float v[16];
#pragma unroll
            for (int nt = 0; nt < 8; nt++) {
                v[nt * 2]     = acc[mt][nt][hf * 2];
                v[nt * 2 + 1] = acc[mt][nt][hf * 2 + 1];
            }
            size_t base = m * DIM + colbase + c2 * 2;
            if (mode == 0) {
                int n = (int)(m & (N_TOK - 1));
                float sc = 1.0f / (float)g_sizes[batch[n]];
#pragma unroll
                for (int k = 0; k < 16; k++) v[k] *= sc;
            } else {
                float s = 0.f, s2 = 0.f;
#pragma unroll
                for (int k = 0; k < 16; k++) { s += v[k]; s2 += v[k] * v[k]; }
                s  += __shfl_xor_sync(0xffffffffu, s, 1);
                s  += __shfl_xor_sync(0xffffffffu, s, 2);
                s2 += __shfl_xor_sync(0xffffffffu, s2, 1);
                s2 += __shfl_xor_sync(0xffffffffu, s2, 2);
                float mu = s * (1.0f / 64.0f);
                float var = s2 * (1.0f / 64.0f) - mu * mu;
                float rs = rsqrtf(var + 1e-6f);
#pragma unroll
                for (int nt = 0; nt < 8; nt++) {
                    int cl = ((warpN + nt * 8 + c2 * 2) & 63); // head-local
                    v[nt * 2]     = (v[nt * 2]     - mu) * rs * lw[cl]     + lb[cl];
                    v[nt * 2 + 1] = (v[nt * 2 + 1] - mu) * rs * lw[cl + 1] + lb[cl + 1];
                }
            }
#pragma unroll
            for (int nt = 0; nt < 8; nt++) {
                ushort2 uh = make_ushort2(
                    __half_as_ushort(__float2half_rn(v[nt * 2])),
                    __half_as_ushort(__float2half_rn(v[nt * 2 + 1])));
                *(ushort2*)((unsigned short*)dh + base + nt * 8) = uh;
            }
        }
    }
#undef QST
#undef Q_ISSUE
}

// ---------------- GEMM2: out = attn_hi @ w_out^T + bias (1-term, 3-stage) ---
#define OG_SMEM (3 * 2 * TEN_BYTES)   // 110592 -> 2 CTAs/SM

__global__ __launch_bounds__(256, 2)
void out_gemm_kernel(const __half* __restrict__ Ah, const __half* __restrict__ Bh,
                     float* __restrict__ C, const float* __restrict__ bias) {
    extern __shared__ __align__(16) char smem[];
    uint32_t sb = smem_u32(smem);
    int tid = threadIdx.x, wid = tid >> 5, lane = tid & 31;
    int warpM = (wid & 3) * 32;
    int warpN = (wid >> 2) * 64;
    int g = lane >> 2, c2 = lane & 3;

    uint32_t aoff = (lane & 15) * 144 + (lane >> 4) * 16;
    uint32_t boff = ((lane & 7) + ((lane >> 4) << 3)) * 144 + ((lane >> 3) & 1) * 16;

    const __half* pAh = Ah + (size_t)blockIdx.y * 128 * KDIM;
    const __half* pBh = Bh + (size_t)blockIdx.x * 128 * KDIM;

#define OST(s, t) (sb + ((s) * 2 + (t)) * TEN_BYTES)
#define O_ISSUE(s, k0)                            \
    do {                                          \
        issue_slab(OST(s, 0), pAh, (k0), tid);    \
        issue_slab(OST(s, 1), pBh, (k0), tid);    \
        asm volatile("cp.async.commit_group;");   \
    } while (0)

    O_ISSUE(0, 0);
    O_ISSUE(1, 64);

    float acc[2][8][4];
#pragma unroll
    for (int i = 0; i < 2; i++)
#pragma unroll
        for (int j = 0; j < 8; j++)
#pragma unroll
            for (int k = 0; k < 4; k++) acc[i][j][k] = 0.0f;

    for (int it = 0; it < 8; it++) {
        int s = it % 3;
        if (it < 7) asm volatile("cp.async.wait_group 1;");
        else        asm volatile("cp.async.wait_group 0;");
        __syncthreads();   // single barrier (3-stage ring)
        uint32_t aA0 = OST(s, 0) + warpM * 144 + aoff;
        uint32_t aB0 = OST(s, 1) + warpN * 144 + boff;
#pragma unroll
        for (int kk = 0; kk < 4; kk++) {
            int ko = kk * 32;
            uint32_t ah[2][4], bf[4][4];
            LDMX4(ah[0], aA0 + ko); LDMX4(ah[1], aA0 + 16 * 144 + ko);
#pragma unroll
            for (int p = 0; p < 4; p++) LDMX4(bf[p], aB0 + p * 16 * 144 + ko);
#pragma unroll
            for (int mt = 0; mt < 2; mt++)
#pragma unroll
                for (int nt = 0; nt < 8; nt++)
                    mma16816(acc[mt][nt], ah[mt], &bf[nt >> 1][(nt & 1) * 2]);
        }
        if (it + 2 < 8) O_ISSUE((it + 2) % 3, (it + 2) * 64);
    }

#pragma unroll
    for (int mt = 0; mt < 2; mt++) {
        size_t m0 = (size_t)blockIdx.y * 128 + warpM + mt * 16 + g;
#pragma unroll
        for (int nt = 0; nt < 8; nt++) {
            int nc = blockIdx.x * 128 + warpN + nt * 8 + c2 * 2;
            float b0 = bias[nc], b1 = bias[nc + 1];
            *(float2*)(C + m0 * DIM + nc) =
                make_float2(acc[mt][nt][0] + b0, acc[mt][nt][1] + b1);
            *(float2*)(C + (m0 + 8) * DIM + nc) =
                make_float2(acc[mt][nt][2] + b0, acc[mt][nt][3] + b1);
        }
    }
#undef OST
#undef O_ISSUE
}

// ---------------- ktvT[b,h,g] (tensor, 1-term: vh*kh) -----------------------
#define KT_SLAB  (64 * 144)
#define KT_STAGE (2 * KT_SLAB)
#define KT_SMEM  (2 * KT_STAGE)      // 36864

__global__ __launch_bounds__(128, 2)
void ktvmma_kernel() {
    int gseg = blockIdx.x & 31;
    int h = (blockIdx.x >> 5) & 7;
    int b = blockIdx.x >> 8;
    int s0 = g_off[gseg], s1 = g_off[gseg + 1];
    int NCH = (s1 - s0 + 63) >> 6;
    if (NCH <= 0) NCH = 1;

    extern __shared__ __align__(16) char smem[];
    uint32_t sb = smem_u32(smem);
    int tid = threadIdx.x, wid = tid >> 5, lane = tid & 31;
    int lg = lane >> 2, c2 = lane & 3;

#define KT_ISSUE(st, c)                                                        \
    do {                                                                       \
        int t0 = s0 + (c) * 64;                                                \
        uint32_t base = sb + (st) * KT_STAGE;                                  \
        char* cbase = smem + (st) * KT_STAGE;                                  \
        _Pragma("unroll")                                                      \
        for (int i = 0; i < 4; i++) {                                          \
            int id = tid + i * 128;                                            \
            int row = id >> 3, ch = id & 7;                                    \
            int tok = t0 + row;                                                \
            uint32_t so = row * 144 + ch * 16;                                 \
            if (tok < s1) {                                                    \
                size_t go = ((size_t)b * N_TOK + tok) * DIM + h * DH + ch * 8; \
                CPA16(base + 0 * KT_SLAB + so, g_k_hi + go);                   \
                CPA16(base + 1 * KT_SLAB + so, g_v_hi + go);                   \
            } else {                                                           \
                uint4 z = make_uint4(0, 0, 0, 0);                              \
                *(uint4*)(cbase + 0 * KT_SLAB + so) = z;                       \
                *(uint4*)(cbase + 1 * KT_SLAB + so) = z;                       \
            }                                                                  \
        }                                                                      \
        asm volatile("cp.async.commit_group;");                                \
    } while (0)

    KT_ISSUE(0, 0);
    if (NCH > 1) KT_ISSUE(1, 1);

    uint32_t aoffT = ((lane & 7) + (lane >> 4) * 8) * 144 + ((lane >> 3) & 1) * 16;
    uint32_t boffT = ((lane & 7) + ((lane >> 3) & 1) * 8) * 144 + (lane >> 4) * 16;

    float acc[8][4];
#pragma unroll
    for (int j = 0; j < 8; j++)
#pragma unroll
        for (int k = 0; k < 4; k++) acc[j][k] = 0.0f;

    for (int c = 0; c < NCH; c++) {
        int st = c & 1;
        if (c + 2 <= NCH) asm volatile("cp.async.wait_group 1;");
        else              asm volatile("cp.async.wait_group 0;");
        __syncthreads();
        uint32_t base = sb + st * KT_STAGE;
        uint32_t aKh = base + 0 * KT_SLAB + boffT;
        uint32_t aVh = base + 1 * KT_SLAB + wid * 32 + aoffT;
#pragma unroll
        for (int kk = 0; kk < 4; kk++) {
            int ko = kk * (16 * 144);
            uint32_t vh[4], kh[4][4];
            LDMX4T(vh, aVh + ko);
#pragma unroll
            for (int nb = 0; nb < 4; nb++)
                LDMX4T(kh[nb], aKh + nb * 32 + ko);
#pragma unroll
            for (int nt = 0; nt < 8; nt++)
                mma16816(acc[nt], vh, &kh[nt >> 1][(nt & 1) * 2]);
        }
        __syncthreads();
        if (c + 2 < NCH) KT_ISSUE(st, c + 2);
    }

    size_t kb = (size_t)blockIdx.x * (DH * DH);
    int r0 = wid * 16 + lg;
#pragma unroll
    for (int nt = 0; nt < 8; nt++) {
        int cidx = nt * 8 + c2 * 2;
        ushort2 u0 = make_ushort2(
            __half_as_ushort(__float2half_rn(acc[nt][0])),
            __half_as_ushort(__float2half_rn(acc[nt][1])));
        ushort2 u1 = make_ushort2(
            __half_as_ushort(__float2half_rn(acc[nt][2])),
            __half_as_ushort(__float2half_rn(acc[nt][3])));
        *(ushort2*)((unsigned short*)g_ktvT_hi + kb + (size_t)r0 * DH + cidx) = u0;
        *(ushort2*)((unsigned short*)g_ktvT_hi + kb + (size_t)(r0 + 8) * DH + cidx) = u1;
    }
#undef KT_ISSUE
}

// ---------------- attn tile = qh @ Th (tensor, 1-term) ----------------------
#define AP_QSLAB (128 * 144)
#define AP_TSLAB (64 * 144)
#define AP_SMEM  (AP_QSLAB + AP_TSLAB)   // 27648

__global__ __launch_bounds__(256, 2)
void applymma_kernel() {
    int h = blockIdx.x, ti = blockIdx.y, b = blockIdx.z;
    int nval = g_tile_nval[ti];
    if (nval == 0) return;
    int gseg = g_tile_g[ti];
    int tok0 = g_tile_tok0[ti];

    extern __shared__ __align__(16) char smem[];
    uint32_t sb = smem_u32(smem);
    uint32_t sQh = sb;
    uint32_t sTh = sb + AP_QSLAB;

    int tid = threadIdx.x, wid = tid >> 5, lane = tid & 31;
    int warpM = (wid & 3) * 32;
    int warpN = (wid >> 2) * 32;
    int g = lane >> 2, c2 = lane & 3;

    {
        size_t qrow0 = (size_t)b * N_TOK + tok0;
#pragma unroll
        for (int t = 0; t < 4; t++) {
            int id = tid + t * 256;          // 0..1023
            int row = id >> 3, ch = id & 7;
            size_t go = (qrow0 + row) * DIM + h * DH + ch * 8;
            CPA16(sQh + row * 144 + ch * 16, (const __half*)g_q_hi + go);
        }
        size_t kbase = ((size_t)((b * HEADS + h) * NGRAPH + gseg)) * DH * DH;
#pragma unroll
        for (int t = 0; t < 2; t++) {
            int id = tid + t * 256;          // 0..511
            int row = id >> 3, ch = id & 7;
            size_t ko = kbase + (size_t)row * DH + ch * 8;
            CPA16(sTh + row * 144 + ch * 16, (const __half*)g_ktvT_hi + ko);
        }
        asm volatile("cp.async.commit_group;");
        asm volatile("cp.async.wait_group 0;");
        __syncthreads();
    }

    uint32_t aoff = (lane & 15) * 144 + (lane >> 4) * 16;
    uint32_t boff = ((lane & 7) + ((lane >> 4) << 3)) * 144 + ((lane >> 3) & 1) * 16;

    float acc[2][4][4];
#pragma unroll
    for (int i = 0; i < 2; i++)
#pragma unroll
        for (int j = 0; j < 4; j++)
#pragma unroll
            for (int k = 0; k < 4; k++) acc[i][j][k] = 0.0f;

    uint32_t aQh = sQh + warpM * 144 + aoff;
    uint32_t aTh = sTh + warpN * 144 + boff;

#pragma unroll
    for (int kk = 0; kk < 4; kk++) {
        int ko = kk * 32;
        uint32_t qh[2][4], bh[2][4];
        LDMX4(qh[0], aQh + ko); LDMX4(qh[1], aQh + 16 * 144 + ko);
        LDMX4(bh[0], aTh + ko); LDMX4(bh[1], aTh + 16 * 144 + ko);
#pragma unroll
        for (int mt = 0; mt < 2; mt++)
#pragma unroll
            for (int nt = 0; nt < 4; nt++)
                mma16816(acc[mt][nt], qh[mt], &bh[nt >> 1][(nt & 1) * 2]);
    }

    // masked epilogue -> attn hi
#pragma unroll
    for (int mt = 0; mt < 2; mt++) {
#pragma unroll
        for (int hf = 0; hf < 2; hf++) {
            int r = warpM + mt * 16 + g + hf * 8;
            if (r < nval) {
                size_t base = ((size_t)b * N_TOK + tok0 + r) * DIM + h * DH + warpN + c2 * 2;
#pragma unroll
                for (int nt = 0; nt < 4; nt++) {
                    float f0 = acc[mt][nt][hf * 2], f1 = acc[mt][nt][hf * 2 + 1];
                    ushort2 uh = make_ushort2(
                        __half_as_ushort(__float2half_rn(f0)),
                        __half_as_ushort(__float2half_rn(f1)));
                    *(ushort2*)((unsigned short*)g_attn_hi + base + nt * 8) = uh;
                }
            }
        }
    }
}

// ---------------- launch ----------------------------------------------------
extern "C" void kernel_launch(void* const* d_in, const int* in_sizes, int n_in,
                              void* d_out, int out_size) {
    const float* x     = (const float*)d_in[0];
    const float* w_qkv = (const float*)d_in[1];
    const float* ln1w  = (const float*)d_in[2];
    const float* ln1b  = (const float*)d_in[3];
    const float* ln2w  = (const float*)d_in[4];
    const float* ln2b  = (const float*)d_in[5];
    const float* w_out = (const float*)d_in[6];
    const float* b_out = (const float*)d_in[7];
    const int*   batch = (const int*)d_in[8];
    float* out = (float*)d_out;

    __half *ah_p, *b1h_p, *b2h_p, *ath_p;
    cudaGetSymbolAddress((void**)&ah_p,  g_a_hi);
    cudaGetSymbolAddress((void**)&b1h_p, g_b1_hi);
    cudaGetSymbolAddress((void**)&b2h_p, g_b2_hi);
    cudaGetSymbolAddress((void**)&ath_p, g_attn_hi);

    cudaFuncSetAttribute(qkv_gemm_kernel, cudaFuncAttributeMaxDynamicSharedMemorySize, QK_SMEM);
    cudaFuncSetAttribute(out_gemm_kernel, cudaFuncAttributeMaxDynamicSharedMemorySize, OG_SMEM);
    cudaFuncSetAttribute(ktvmma_kernel,   cudaFuncAttributeMaxDynamicSharedMemorySize, KT_SMEM);
    cudaFuncSetAttribute(applymma_kernel, cudaFuncAttributeMaxDynamicSharedMemorySize, AP_SMEM);

    // 0) prep: hist + tile tables + all conversions (one launch)
    prep_kernel<<<4097, 256>>>(x, w_qkv, w_out, batch);

    // 1) qkv GEMM (1-term fp16, 3-stage) + fused epilogue (all hi-only)
    qkv_gemm_kernel<<<dim3(QKV3 / 128, M_ROWS / 128), 256, QK_SMEM>>>(
        ah_p, b1h_p, batch, ln1w, ln1b, ln2w, ln2b);

    // 2) ktvT per (b,h,g) (tensor, 1-term vh*kh)
    ktvmma_kernel<<<B_SZ * HEADS * NGRAPH, 128, KT_SMEM>>>();

    // 3) attn = qh @ Th (tensor, 1-term, masked ragged tiles)
    applymma_kernel<<<dim3(HEADS, TILEMAX, B_SZ), 256, AP_SMEM>>>();

    // 4) out = attn_hi @ w_outT + bias (1-term, 3-stage)
    out_gemm_kernel<<<dim3(DIM / 128, M_ROWS / 128), 256, OG_SMEM>>>(
        ath_p, b2h_p, out, b_out);
}

// round 17
// speedup vs baseline: 1.3460x; 1.0280x over previous
#include <cuda_runtime.h>
#include <cuda_fp16.h>
#include <cstdint>

// ---------------- problem constants (fixed by setup_inputs) ----------------
#define B_SZ   2
#define N_TOK  32768
#define DIM    512
#define HEADS  8
#define DH     64
#define NGRAPH 32
#define QKV3   1536
#define M_ROWS (B_SZ * N_TOK)          // 65536
#define KDIM   512

// ---------------- device scratch (static; no allocations allowed) ----------
__device__ __half g_a_hi[(size_t)M_ROWS * KDIM];
__device__ __half g_b1_hi[QKV3 * KDIM];
__device__ __half g_b2_hi[DIM * KDIM];
__device__ __half g_q_hi[((size_t)M_ROWS + 128) * DIM];   // +128 slack rows
__device__ __half g_k_hi[(size_t)M_ROWS * DIM];
__device__ __half g_v_hi[(size_t)M_ROWS * DIM];
__device__ __half g_attn_hi[(size_t)M_ROWS * DIM];
__device__ int    g_sizes[NGRAPH];
__device__ int    g_off [NGRAPH + 1];

// ---------------- helpers ---------------------------------------------------
__device__ __forceinline__ uint32_t smem_u32(const void* p) {
    uint32_t a;
    asm("{ .reg .u64 t; cvta.to.shared.u64 t, %1; cvt.u32.u64 %0, t; }"
        : "=r"(a) : "l"(p));
    return a;
}
__device__ __forceinline__ void mma16816(float* d, const uint32_t* a, const uint32_t* b) {
    asm volatile(
        "mma.sync.aligned.m16n8k16.row.col.f32.f16.f16.f32 "
        "{%0,%1,%2,%3}, {%4,%5,%6,%7}, {%8,%9}, {%0,%1,%2,%3};"
        : "+f"(d[0]), "+f"(d[1]), "+f"(d[2]), "+f"(d[3])
        : "r"(a[0]), "r"(a[1]), "r"(a[2]), "r"(a[3]), "r"(b[0]), "r"(b[1]));
}
#define LDMX4(r, addr) \
    asm volatile("ldmatrix.sync.aligned.m8n8.x4.shared.b16 {%0,%1,%2,%3}, [%4];" \
                 : "=r"((r)[0]), "=r"((r)[1]), "=r"((r)[2]), "=r"((r)[3]) : "r"(addr))
#define LDMX4T(r, addr) \
    asm volatile("ldmatrix.sync.aligned.m8n8.x4.trans.shared.b16 {%0,%1,%2,%3}, [%4];" \
                 : "=r"((r)[0]), "=r"((r)[1]), "=r"((r)[2]), "=r"((r)[3]) : "r"(addr))
#define CPA16(s, gp) \
    asm volatile("cp.async.cg.shared.global [%0], [%1], 16;" :: "r"(s), "l"(gp))

__device__ __forceinline__ ushort4 round4(float4 v) {
    ushort4 r;
    r.x = __half_as_ushort(__float2half_rn(v.x));
    r.y = __half_as_ushort(__float2half_rn(v.y));
    r.z = __half_as_ushort(__float2half_rn(v.z));
    r.w = __half_as_ushort(__float2half_rn(v.w));
    return r;
}

// ---------------- prep: hist + all fp32->fp16 conversions (one launch) ------
__global__ void prep_kernel(const float* __restrict__ x,
                            const float* __restrict__ w1,
                            const float* __restrict__ w2,
                            const int* __restrict__ batch) {
    if (blockIdx.x == gridDim.x - 1) {
        __shared__ int cnt[NGRAPH];
        int tid = threadIdx.x;
        if (tid < NGRAPH) cnt[tid] = 0;
        __syncthreads();
        for (int i = tid; i < N_TOK; i += 256) atomicAdd(&cnt[batch[i]], 1);
        __syncthreads();
        if (tid == 0) {
            int off = 0;
            for (int g = 0; g < NGRAPH; g++) {
                g_off[g] = off; g_sizes[g] = cnt[g]; off += cnt[g];
            }
            g_off[NGRAPH] = off;
        }
        return;
    }
    const long nx = (long)M_ROWS * KDIM / 4;
    const long n1 = (long)QKV3 * KDIM / 4;
    const long n2 = (long)DIM * KDIM / 4;
    long i = (long)blockIdx.x * blockDim.x + threadIdx.x;
    long stride = (long)(gridDim.x - 1) * blockDim.x;
    for (; i < nx + n1 + n2; i += stride) {
        if (i < nx)
            ((ushort4*)g_a_hi)[i] = round4(((const float4*)x)[i]);
        else if (i < nx + n1)
            ((ushort4*)g_b1_hi)[i - nx] = round4(((const float4*)w1)[i - nx]);
        else
            ((ushort4*)g_b2_hi)[i - nx - n1] = round4(((const float4*)w2)[i - nx - n1]);
    }
}

#define TEN_BYTES (128 * 144)

__device__ __forceinline__ void issue_slab(uint32_t sdst, const __half* g,
                                           int k0, int tid) {
#pragma unroll
    for (int t = 0; t < 4; t++) {
        int id  = tid + t * 256;
        int row = id >> 3, col = id & 7;
        CPA16(sdst + row * 144 + col * 16, g + (size_t)row * KDIM + k0 + col * 8);
    }
}

// ---------------- GEMM1: qkv = x16 @ w16^T (1-term fp16, 3-stage ring) ------
// epilogue: q scale->hi, k LN(ln1)->hi, v LN(ln2)->hi
#define QK_SMEM (3 * 2 * TEN_BYTES)   // 110592 -> 2 CTAs/SM

__global__ __launch_bounds__(256, 2)
void qkv_gemm_kernel(const __half* __restrict__ Ah, const __half* __restrict__ Bh,
                     const int* __restrict__ batch,
                     const float* __restrict__ ln1w, const float* __restrict__ ln1b,
                     const float* __restrict__ ln2w, const float* __restrict__ ln2b) {
    extern __shared__ __align__(16) char smem[];
    uint32_t sb = smem_u32(smem);
    int tid = threadIdx.x, wid = tid >> 5, lane = tid & 31;
    int warpM = (wid & 3) * 32;
    int warpN = (wid >> 2) * 64;
    int g = lane >> 2, c2 = lane & 3;

    uint32_t aoff = (lane & 15) * 144 + (lane >> 4) * 16;
    uint32_t boff = ((lane & 7) + ((lane >> 4) << 3)) * 144 + ((lane >> 3) & 1) * 16;

    const __half* pAh = Ah + (size_t)blockIdx.y * 128 * KDIM;
    const __half* pBh = Bh + (size_t)blockIdx.x * 128 * KDIM;

#define QST(s, t) (sb + ((s) * 2 + (t)) * TEN_BYTES)
#define Q_ISSUE(s, k0)                            \
    do {                                          \
        issue_slab(QST(s, 0), pAh, (k0), tid);    \
        issue_slab(QST(s, 1), pBh, (k0), tid);    \
        asm volatile("cp.async.commit_group;");   \
    } while (0)

    Q_ISSUE(0, 0);
    Q_ISSUE(1, 64);

    float acc[2][8][4];
#pragma unroll
    for (int i = 0; i < 2; i++)
#pragma unroll
        for (int j = 0; j < 8; j++)
#pragma unroll
            for (int k = 0; k < 4; k++) acc[i][j][k] = 0.0f;

    for (int it = 0; it < 8; it++) {
        int s = it % 3;
        if (it < 7) asm volatile("cp.async.wait_group 1;");
        else        asm volatile("cp.async.wait_group 0;");
        __syncthreads();   // single barrier: frees stage (it+2)%3 too
        uint32_t aA0 = QST(s, 0) + warpM * 144 + aoff;
        uint32_t aB0 = QST(s, 1) + warpN * 144 + boff;
#pragma unroll
        for (int kk = 0; kk < 4; kk++) {
            int ko = kk * 32;
            uint32_t ah[2][4], bf[4][4];
            LDMX4(ah[0], aA0 + ko); LDMX4(ah[1], aA0 + 16 * 144 + ko);
#pragma unroll
            for (int p = 0; p < 4; p++) LDMX4(bf[p], aB0 + p * 16 * 144 + ko);
#pragma unroll
            for (int mt = 0; mt < 2; mt++)
#pragma unroll
                for (int nt = 0; nt < 8; nt++)
                    mma16816(acc[mt][nt], ah[mt], &bf[nt >> 1][(nt & 1) * 2]);
        }
        if (it + 2 < 8) Q_ISSUE((it + 2) % 3, (it + 2) * 64);
    }

    // epilogue: q scale / k LN / v LN, all -> single fp16
    int mode = blockIdx.x >> 2;          // 0 q, 1 k, 2 v
    const float* lw = (mode == 1) ? ln1w : ln2w;
    const float* lb = (mode == 1) ? ln1b : ln2b;
    __half* dh = (mode == 0) ? g_q_hi : (mode == 1) ? g_k_hi : g_v_hi;
    int colbase = blockIdx.x * 128 - mode * 512 + warpN;   // 0..511 in buffer
#pragma unroll
    for (int mt = 0; mt < 2; mt++) {
#pragma unroll
        for (int hf = 0; hf < 2; hf++) {
            size_t m = (size_t)blockIdx.y * 128 + warpM + mt * 16 + g + hf * 8;
            float v[16];
#pragma unroll
            for (int nt = 0; nt < 8; nt++) {
                v[nt * 2]     = acc[mt][nt][hf * 2];
                v[nt * 2 + 1] = acc[mt][nt][hf * 2 + 1];
            }
            size_t base = m * DIM + colbase + c2 * 2;
            if (mode == 0) {
                int n = (int)(m & (N_TOK - 1));
                float sc = 1.0f / (float)g_sizes[batch[n]];
#pragma unroll
                for (int k = 0; k < 16; k++) v[k] *= sc;
            } else {
                float s = 0.f, s2 = 0.f;
#pragma unroll
                for (int k = 0; k < 16; k++) { s += v[k]; s2 += v[k] * v[k]; }
                s  += __shfl_xor_sync(0xffffffffu, s, 1);
                s  += __shfl_xor_sync(0xffffffffu, s, 2);
                s2 += __shfl_xor_sync(0xffffffffu, s2, 1);
                s2 += __shfl_xor_sync(0xffffffffu, s2, 2);
                float mu = s * (1.0f / 64.0f);
                float var = s2 * (1.0f / 64.0f) - mu * mu;
                float rs = rsqrtf(var + 1e-6f);
#pragma unroll
                for (int nt = 0; nt < 8; nt++) {
                    int cl = ((warpN + nt * 8 + c2 * 2) & 63); // head-local
                    v[nt * 2]     = (v[nt * 2]     - mu) * rs * lw[cl]     + lb[cl];
                    v[nt * 2 + 1] = (v[nt * 2 + 1] - mu) * rs * lw[cl + 1] + lb[cl + 1];
                }
            }
#pragma unroll
            for (int nt = 0; nt < 8; nt++) {
                ushort2 uh = make_ushort2(
                    __half_as_ushort(__float2half_rn(v[nt * 2])),
                    __half_as_ushort(__float2half_rn(v[nt * 2 + 1])));
                *(ushort2*)((unsigned short*)dh + base + nt * 8) = uh;
            }
        }
    }
#undef QST
#undef Q_ISSUE
}

// ---------------- GEMM2: out = attn_hi @ w_out^T + bias (1-term, 3-stage) ---
#define OG_SMEM (3 * 2 * TEN_BYTES)   // 110592 -> 2 CTAs/SM

__global__ __launch_bounds__(256, 2)
void out_gemm_kernel(const __half* __restrict__ Ah, const __half* __restrict__ Bh,
                     float* __restrict__ C, const float* __restrict__ bias) {
    extern __shared__ __align__(16) char smem[];
    uint32_t sb = smem_u32(smem);
    int tid = threadIdx.x, wid = tid >> 5, lane = tid & 31;
    int warpM = (wid & 3) * 32;
    int warpN = (wid >> 2) * 64;
    int g = lane >> 2, c2 = lane & 3;

    uint32_t aoff = (lane & 15) * 144 + (lane >> 4) * 16;
    uint32_t boff = ((lane & 7) + ((lane >> 4) << 3)) * 144 + ((lane >> 3) & 1) * 16;

    const __half* pAh = Ah + (size_t)blockIdx.y * 128 * KDIM;
    const __half* pBh = Bh + (size_t)blockIdx.x * 128 * KDIM;

#define OST(s, t) (sb + ((s) * 2 + (t)) * TEN_BYTES)
#define O_ISSUE(s, k0)                            \
    do {                                          \
        issue_slab(OST(s, 0), pAh, (k0), tid);    \
        issue_slab(OST(s, 1), pBh, (k0), tid);    \
        asm volatile("cp.async.commit_group;");   \
    } while (0)

    O_ISSUE(0, 0);
    O_ISSUE(1, 64);

    float acc[2][8][4];
#pragma unroll
    for (int i = 0; i < 2; i++)
#pragma unroll
        for (int j = 0; j < 8; j++)
#pragma unroll
            for (int k = 0; k < 4; k++) acc[i][j][k] = 0.0f;

    for (int it = 0; it < 8; it++) {
        int s = it % 3;
        if (it < 7) asm volatile("cp.async.wait_group 1;");
        else        asm volatile("cp.async.wait_group 0;");
        __syncthreads();   // single barrier (3-stage ring)
        uint32_t aA0 = OST(s, 0) + warpM * 144 + aoff;
        uint32_t aB0 = OST(s, 1) + warpN * 144 + boff;
#pragma unroll
        for (int kk = 0; kk < 4; kk++) {
            int ko = kk * 32;
            uint32_t ah[2][4], bf[4][4];
            LDMX4(ah[0], aA0 + ko); LDMX4(ah[1], aA0 + 16 * 144 + ko);
#pragma unroll
            for (int p = 0; p < 4; p++) LDMX4(bf[p], aB0 + p * 16 * 144 + ko);
#pragma unroll
            for (int mt = 0; mt < 2; mt++)
#pragma unroll
                for (int nt = 0; nt < 8; nt++)
                    mma16816(acc[mt][nt], ah[mt], &bf[nt >> 1][(nt & 1) * 2]);
        }
        if (it + 2 < 8) O_ISSUE((it + 2) % 3, (it + 2) * 64);
    }

#pragma unroll
    for (int mt = 0; mt < 2; mt++) {
        size_t m0 = (size_t)blockIdx.y * 128 + warpM + mt * 16 + g;
#pragma unroll
        for (int nt = 0; nt < 8; nt++) {
            int nc = blockIdx.x * 128 + warpN + nt * 8 + c2 * 2;
            float b0 = bias[nc], b1 = bias[nc + 1];
            *(float2*)(C + m0 * DIM + nc) =
                make_float2(acc[mt][nt][0] + b0, acc[mt][nt][1] + b1);
            *(float2*)(C + (m0 + 8) * DIM + nc) =
                make_float2(acc[mt][nt][2] + b0, acc[mt][nt][3] + b1);
        }
    }
#undef OST
#undef O_ISSUE
}

// ---------------- fused segment kernel: ktvT (smem) + apply -----------------
// one CTA per (b,h,g), 256 threads.
// phase 1: T[e][d] = sum_tok V[tok][e]*K[tok][d] -> fp16 in smem
// phase 2: stream q tiles (128 rows) against resident T, write attn.
#define FK_T     0                       // T slab: 64 rows x 144B = 9216
#define FK_WORK  9216                    // 2 stages x 18432
#define FK_STAGE 18432
#define FK_SMEM  (9216 + 2 * FK_STAGE)   // 46080 -> 2 CTAs/SM

__global__ __launch_bounds__(256, 2)
void seg_kernel() {
    int gseg = blockIdx.x & 31;
    int h = (blockIdx.x >> 5) & 7;
    int b = blockIdx.x >> 8;
    int s0 = g_off[gseg], s1 = g_off[gseg + 1];
    int S = s1 - s0;
    if (S <= 0) return;                  // uniform across block

    extern __shared__ __align__(16) char smem[];
    uint32_t sb = smem_u32(smem);
    int tid = threadIdx.x, wid = tid >> 5, lane = tid & 31;
    int lg = lane >> 2, c2 = lane & 3;

    // ---------- phase 1: ktvT ----------
    int NCH = (S + 63) >> 6;

#define FK_KV_ISSUE(st, c)                                                     \
    do {                                                                       \
        int t0 = s0 + (c) * 64;                                                \
        uint32_t base = sb + FK_WORK + (st) * FK_STAGE;                        \
        char* cbase = smem + FK_WORK + (st) * FK_STAGE;                        \
        _Pragma("unroll")                                                      \
        for (int i = 0; i < 2; i++) {                                          \
            int id = tid + i * 256;          /* 0..511 */                      \
            int row = id >> 3, ch = id & 7;                                    \
            int tok = t0 + row;                                                \
            uint32_t so = row * 144 + ch * 16;                                 \
            if (tok < s1) {                                                    \
                size_t go = ((size_t)b * N_TOK + tok) * DIM + h * DH + ch * 8; \
                CPA16(base + so, g_k_hi + go);                                 \
                CPA16(base + 9216 + so, g_v_hi + go);                          \
            } else {                                                           \
                uint4 z = make_uint4(0, 0, 0, 0);                              \
                *(uint4*)(cbase + so) = z;                                     \
                *(uint4*)(cbase + 9216 + so) = z;                              \
            }                                                                  \
        }                                                                      \
        asm volatile("cp.async.commit_group;");                                \
    } while (0)

    FK_KV_ISSUE(0, 0);
    if (NCH > 1) FK_KV_ISSUE(1, 1);

    uint32_t aoffT = ((lane & 7) + (lane >> 4) * 8) * 144 + ((lane >> 3) & 1) * 16;
    uint32_t boffT = ((lane & 7) + ((lane >> 3) & 1) * 8) * 144 + (lane >> 4) * 16;

    float acc[8][4];
#pragma unroll
    for (int j = 0; j < 8; j++)
#pragma unroll
        for (int k = 0; k < 4; k++) acc[j][k] = 0.0f;

    for (int c = 0; c < NCH; c++) {
        int st = c & 1;
        if (c + 2 <= NCH) asm volatile("cp.async.wait_group 1;");
        else              asm volatile("cp.async.wait_group 0;");
        __syncthreads();
        if (wid < 4) {
            uint32_t base = sb + FK_WORK + st * FK_STAGE;
            uint32_t aKh = base + boffT;
            uint32_t aVh = base + 9216 + wid * 32 + aoffT;
#pragma unroll
            for (int kk = 0; kk < 4; kk++) {
                int ko = kk * (16 * 144);
                uint32_t vh[4], kh[4][4];
                LDMX4T(vh, aVh + ko);
#pragma unroll
                for (int nb = 0; nb < 4; nb++)
                    LDMX4T(kh[nb], aKh + nb * 32 + ko);
#pragma unroll
                for (int nt = 0; nt < 8; nt++)
                    mma16816(acc[nt], vh, &kh[nt >> 1][(nt & 1) * 2]);
            }
        }
        __syncthreads();
        if (c + 2 < NCH) FK_KV_ISSUE(st, c + 2);
    }

    // store T to smem (fp16, 144B pitch) — warps 0..3 hold the accumulators
    if (wid < 4) {
        int r0 = wid * 16 + lg;
#pragma unroll
        for (int nt = 0; nt < 8; nt++) {
            int cb = nt * 16 + c2 * 4;   // byte col
            *(ushort2*)(smem + FK_T + r0 * 144 + cb) = make_ushort2(
                __half_as_ushort(__float2half_rn(acc[nt][0])),
                __half_as_ushort(__float2half_rn(acc[nt][1])));
            *(ushort2*)(smem + FK_T + (r0 + 8) * 144 + cb) = make_ushort2(
                __half_as_ushort(__float2half_rn(acc[nt][2])),
                __half_as_ushort(__float2half_rn(acc[nt][3])));
        }
    }
    __syncthreads();

    // ---------- phase 2: apply ----------
    int ntile = (S + 127) >> 7;
    size_t qrow0 = (size_t)b * N_TOK + s0;

#define FK_Q_ISSUE(st, t)                                                      \
    do {                                                                       \
        uint32_t base = sb + FK_WORK + (st) * FK_STAGE;                        \
        size_t r0g = qrow0 + (size_t)(t) * 128;                                \
        _Pragma("unroll")                                                      \
        for (int i = 0; i < 4; i++) {                                          \
            int id = tid + i * 256;          /* 0..1023 */                     \
            int row = id >> 3, ch = id & 7;                                    \
            size_t go = (r0g + row) * DIM + h * DH + ch * 8;                   \
            CPA16(base + row * 144 + ch * 16, g_q_hi + go);                    \
        }                                                                      \
        asm volatile("cp.async.commit_group;");                                \
    } while (0)

    FK_Q_ISSUE(0, 0);
    if (ntile > 1) FK_Q_ISSUE(1, 1);

    int warpM = (wid & 3) * 32;
    int warpN = (wid >> 2) * 32;
    uint32_t aoff = (lane & 15) * 144 + (lane >> 4) * 16;
    uint32_t boff = ((lane & 7) + ((lane >> 4) << 3)) * 144 + ((lane >> 3) & 1) * 16;
    uint32_t aTh = sb + FK_T + warpN * 144 + boff;

    for (int t = 0; t < ntile; t++) {
        int st = t & 1;
        if (t + 2 <= ntile) asm volatile("cp.async.wait_group 1;");
        else                asm volatile("cp.async.wait_group 0;");
        __syncthreads();
        uint32_t aQh = sb + FK_WORK + st * FK_STAGE + warpM * 144 + aoff;

        float ac[2][4][4];
#pragma unroll
        for (int i = 0; i < 2; i++)
#pragma unroll
            for (int j = 0; j < 4; j++)
#pragma unroll
                for (int k = 0; k < 4; k++) ac[i][j][k] = 0.0f;

#pragma unroll
        for (int kk = 0; kk < 4; kk++) {
            int ko = kk * 32;
            uint32_t qh[2][4], bh[2][4];
            LDMX4(qh[0], aQh + ko); LDMX4(qh[1], aQh + 16 * 144 + ko);
            LDMX4(bh[0], aTh + ko); LDMX4(bh[1], aTh + 16 * 144 + ko);
#pragma unroll
            for (int mt = 0; mt < 2; mt++)
#pragma unroll
                for (int nt = 0; nt < 4; nt++)
                    mma16816(ac[mt][nt], qh[mt], &bh[nt >> 1][(nt & 1) * 2]);
        }

        // masked epilogue
        int nval = S - t * 128; if (nval > 128) nval = 128;
        int g2 = lane >> 2;
#pragma unroll
        for (int mt = 0; mt < 2; mt++) {
#pragma unroll
            for (int hf = 0; hf < 2; hf++) {
                int r = warpM + mt * 16 + g2 + hf * 8;
                if (r < nval) {
                    size_t base = (qrow0 + (size_t)t * 128 + r) * DIM + h * DH + warpN + c2 * 2;
#pragma unroll
                    for (int nt = 0; nt < 4; nt++) {
                        ushort2 uh = make_ushort2(
                            __half_as_ushort(__float2half_rn(ac[mt][nt][hf * 2])),
                            __half_as_ushort(__float2half_rn(ac[mt][nt][hf * 2 + 1])));
                        *(ushort2*)((unsigned short*)g_attn_hi + base + nt * 8) = uh;
                    }
                }
            }
        }
        __syncthreads();
        if (t + 2 < ntile) FK_Q_ISSUE(st, t + 2);
    }
#undef FK_KV_ISSUE
#undef FK_Q_ISSUE
}

// ---------------- launch ----------------------------------------------------
extern "C" void kernel_launch(void* const* d_in, const int* in_sizes, int n_in,
                              void* d_out, int out_size) {
    const float* x     = (const float*)d_in[0];
    const float* w_qkv = (const float*)d_in[1];
    const float* ln1w  = (const float*)d_in[2];
    const float* ln1b  = (const float*)d_in[3];
    const float* ln2w  = (const float*)d_in[4];
    const float* ln2b  = (const float*)d_in[5];
    const float* w_out = (const float*)d_in[6];
    const float* b_out = (const float*)d_in[7];
    const int*   batch = (const int*)d_in[8];
    float* out = (float*)d_out;

    __half *ah_p, *b1h_p, *b2h_p, *ath_p;
    cudaGetSymbolAddress((void**)&ah_p,  g_a_hi);
    cudaGetSymbolAddress((void**)&b1h_p, g_b1_hi);
    cudaGetSymbolAddress((void**)&b2h_p, g_b2_hi);
    cudaGetSymbolAddress((void**)&ath_p, g_attn_hi);

    cudaFuncSetAttribute(qkv_gemm_kernel, cudaFuncAttributeMaxDynamicSharedMemorySize, QK_SMEM);
    cudaFuncSetAttribute(out_gemm_kernel, cudaFuncAttributeMaxDynamicSharedMemorySize, OG_SMEM);
    cudaFuncSetAttribute(seg_kernel,      cudaFuncAttributeMaxDynamicSharedMemorySize, FK_SMEM);

    // 0) prep: hist + conversions
    prep_kernel<<<4097, 256>>>(x, w_qkv, w_out, batch);

    // 1) qkv GEMM + fused epilogue
    qkv_gemm_kernel<<<dim3(QKV3 / 128, M_ROWS / 128), 256, QK_SMEM>>>(
        ah_p, b1h_p, batch, ln1w, ln1b, ln2w, ln2b);

    // 2) fused ktvT + apply per (b,h,g)
    seg_kernel<<<B_SZ * HEADS * NGRAPH, 256, FK_SMEM>>>();

    // 3) out = attn_hi @ w_outT + bias
    out_gemm_kernel<<<dim3(DIM / 128, M_ROWS / 128), 256, OG_SMEM>>>(
        ath_p, b2h_p, out, b_out);
}